// round 2
// baseline (speedup 1.0000x reference)
#include <cuda_runtime.h>

#define D 128
#define MAXN 50000

// Scratch (no allocations allowed in kernel_launch).
__device__ __align__(16) float g_z[(size_t)MAXN * D];   // z = x + agg, later z2 = h@W2+b2
__device__ __align__(16) float g_h[(size_t)MAXN * D];   // hidden = relu(z@W1+b1)
__device__ __align__(16) float g_stats[2 * D];          // col sum, col sumsq
__device__ __align__(16) float g_scale[D];
__device__ __align__(16) float g_shift[D];
__device__ int g_idx_is64;                              // 1 if edge_index is int64

// ---------------------------------------------------------------------------
// Probe edge_index dtype: int64 values must all be in [0, N). For int32 data
// read as int64, the high word is a random index (nonzero w.h.p.), so the
// check fails essentially always.
// ---------------------------------------------------------------------------
__global__ void probe_idx_type(const void* ei, int E, int N) {
    const long long* p = (const long long*)ei;
    int n = E < 64 ? E : 64;
    int ok = 1;
    for (int i = 0; i < n; ++i) {
        long long v = p[i];
        if (v < 0 || v >= N) { ok = 0; break; }
    }
    g_idx_is64 = ok;
}

// ---------------------------------------------------------------------------
// z = x  (vectorized copy into scratch)
// ---------------------------------------------------------------------------
__global__ void copy_init(const float4* __restrict__ x, int n4) {
    int i = blockIdx.x * blockDim.x + threadIdx.x;
    if (i < n4) reinterpret_cast<float4*>(g_z)[i] = x[i];
}

// ---------------------------------------------------------------------------
// z[dst] += x[src] for each edge. One warp per edge, one float4 per lane.
// Index dtype resolved at runtime via g_idx_is64 (uniform branch).
// ---------------------------------------------------------------------------
__global__ void scatter_add(const float4* __restrict__ x,
                            const void* __restrict__ ei,
                            int E, int N) {
    int w = (blockIdx.x * blockDim.x + threadIdx.x) >> 5;
    int lane = threadIdx.x & 31;
    if (w >= E) return;
    int s, d;
    if (g_idx_is64) {
        const long long* p = (const long long*)ei;
        s = (int)__ldg(&p[w]);
        d = (int)__ldg(&p[E + w]);
    } else {
        const int* p = (const int*)ei;
        s = __ldg(&p[w]);
        d = __ldg(&p[E + w]);
    }
    if ((unsigned)s >= (unsigned)N || (unsigned)d >= (unsigned)N) return;
    float4 v = x[(size_t)s * (D / 4) + lane];
    atomicAdd(reinterpret_cast<float4*>(g_z) + (size_t)d * (D / 4) + lane, v);
}

// ---------------------------------------------------------------------------
// C[N,128] = act(A[N,128] @ W[128,128] + bias)
// FIRST=1: A=g_z, C=g_h (relu).  FIRST=0: A=g_h, C=g_z (linear).
// Classic 128x128x8 tiling, 256 threads, 8x8 thread tile as 2x2 blocks of 4x4.
// ---------------------------------------------------------------------------
template <int FIRST>
__global__ __launch_bounds__(256) void gemm_bias_act(
    const float* __restrict__ W, const float* __restrict__ bias,
    int N, int doRelu) {
    const float* __restrict__ A = FIRST ? g_z : g_h;
    float* __restrict__ C = FIRST ? g_h : g_z;

    __shared__ float As[8][132];   // padded: conflict-free transposed stores
    __shared__ float Bs[8][128];

    int tid = threadIdx.x;
    int rowBase = blockIdx.x * 128;
    int tx = tid & 15;    // column group (cols tx*4.. and 64+tx*4..)
    int ty = tid >> 4;    // row group    (rows ty*4.. and 64+ty*4..)

    int aRow = tid >> 1;          // 0..127
    int aK4  = (tid & 1) * 4;     // 0 or 4
    int bK   = tid >> 5;          // 0..7
    int bCol = (tid & 31) * 4;    // 0..124

    float acc00[4][4] = {}, acc01[4][4] = {}, acc10[4][4] = {}, acc11[4][4] = {};

    for (int k0 = 0; k0 < D; k0 += 8) {
        int gr = rowBase + aRow;
        if (gr >= N) gr = N - 1;  // clamp (results discarded for OOB rows)
        float4 av = *reinterpret_cast<const float4*>(A + (size_t)gr * D + k0 + aK4);
        As[aK4 + 0][aRow] = av.x;
        As[aK4 + 1][aRow] = av.y;
        As[aK4 + 2][aRow] = av.z;
        As[aK4 + 3][aRow] = av.w;
        *reinterpret_cast<float4*>(&Bs[bK][bCol]) =
            *reinterpret_cast<const float4*>(W + (size_t)(k0 + bK) * D + bCol);
        __syncthreads();

#pragma unroll
        for (int k = 0; k < 8; ++k) {
            float4 a0 = *reinterpret_cast<const float4*>(&As[k][ty * 4]);
            float4 a1 = *reinterpret_cast<const float4*>(&As[k][64 + ty * 4]);
            float4 b0 = *reinterpret_cast<const float4*>(&Bs[k][tx * 4]);
            float4 b1 = *reinterpret_cast<const float4*>(&Bs[k][64 + tx * 4]);
            float ar0[4] = {a0.x, a0.y, a0.z, a0.w};
            float ar1[4] = {a1.x, a1.y, a1.z, a1.w};
            float br0[4] = {b0.x, b0.y, b0.z, b0.w};
            float br1[4] = {b1.x, b1.y, b1.z, b1.w};
#pragma unroll
            for (int i = 0; i < 4; ++i)
#pragma unroll
                for (int j = 0; j < 4; ++j) {
                    acc00[i][j] += ar0[i] * br0[j];
                    acc01[i][j] += ar0[i] * br1[j];
                    acc10[i][j] += ar1[i] * br0[j];
                    acc11[i][j] += ar1[i] * br1[j];
                }
        }
        __syncthreads();
    }

    float4 bb0 = *reinterpret_cast<const float4*>(&bias[tx * 4]);
    float4 bb1 = *reinterpret_cast<const float4*>(&bias[64 + tx * 4]);
    float bc0[4] = {bb0.x, bb0.y, bb0.z, bb0.w};
    float bc1[4] = {bb1.x, bb1.y, bb1.z, bb1.w};

#pragma unroll
    for (int i = 0; i < 4; ++i) {
        int r = rowBase + ty * 4 + i;
        if (r < N) {
            float4 o0, o1;
            float* p0 = &o0.x; float* p1 = &o1.x;
#pragma unroll
            for (int j = 0; j < 4; ++j) {
                float v0 = acc00[i][j] + bc0[j];
                float v1 = acc01[i][j] + bc1[j];
                if (doRelu) { v0 = fmaxf(v0, 0.f); v1 = fmaxf(v1, 0.f); }
                p0[j] = v0; p1[j] = v1;
            }
            *reinterpret_cast<float4*>(C + (size_t)r * D + tx * 4) = o0;
            *reinterpret_cast<float4*>(C + (size_t)r * D + 64 + tx * 4) = o1;
        }
        int r2 = rowBase + 64 + ty * 4 + i;
        if (r2 < N) {
            float4 o0, o1;
            float* p0 = &o0.x; float* p1 = &o1.x;
#pragma unroll
            for (int j = 0; j < 4; ++j) {
                float v0 = acc10[i][j] + bc0[j];
                float v1 = acc11[i][j] + bc1[j];
                if (doRelu) { v0 = fmaxf(v0, 0.f); v1 = fmaxf(v1, 0.f); }
                p0[j] = v0; p1[j] = v1;
            }
            *reinterpret_cast<float4*>(C + (size_t)r2 * D + tx * 4) = o0;
            *reinterpret_cast<float4*>(C + (size_t)r2 * D + 64 + tx * 4) = o1;
        }
    }
}

// ---------------------------------------------------------------------------
// BatchNorm statistics over nodes (columns of g_z)
// ---------------------------------------------------------------------------
__global__ void zero_stats() {
    g_stats[threadIdx.x] = 0.f;
}

__global__ void col_stats(int N) {
    __shared__ float ssum[256], ssq[256];
    int c = threadIdx.x & 127;
    int half = threadIdx.x >> 7;
    float s = 0.f, q = 0.f;
    for (int r = blockIdx.x * 2 + half; r < N; r += gridDim.x * 2) {
        float v = g_z[(size_t)r * D + c];
        s += v; q += v * v;
    }
    ssum[threadIdx.x] = s; ssq[threadIdx.x] = q;
    __syncthreads();
    if (half == 0) {
        atomicAdd(&g_stats[c],     ssum[threadIdx.x] + ssum[threadIdx.x + 128]);
        atomicAdd(&g_stats[D + c], ssq[threadIdx.x]  + ssq[threadIdx.x + 128]);
    }
}

__global__ void bn_finalize(const float* __restrict__ gamma,
                            const float* __restrict__ beta, float invN) {
    int c = threadIdx.x;
    float s = g_stats[c], q = g_stats[D + c];
    float mean = s * invN;
    float var = fmaxf(q * invN - mean * mean, 0.f);
    float a = gamma[c] * rsqrtf(var + 1e-5f);
    g_scale[c] = a;
    g_shift[c] = beta[c] - mean * a;
}

__global__ void bn_relu(float4* __restrict__ y, int n4) {
    int i = blockIdx.x * blockDim.x + threadIdx.x;
    if (i >= n4) return;
    int c = i & (D / 4 - 1);
    float4 a = *reinterpret_cast<const float4*>(&g_scale[c * 4]);
    float4 b = *reinterpret_cast<const float4*>(&g_shift[c * 4]);
    float4 v = reinterpret_cast<const float4*>(g_z)[i];
    v.x = fmaxf(v.x * a.x + b.x, 0.f);
    v.y = fmaxf(v.y * a.y + b.y, 0.f);
    v.z = fmaxf(v.z * a.z + b.z, 0.f);
    v.w = fmaxf(v.w * a.w + b.w, 0.f);
    y[i] = v;
}

// ---------------------------------------------------------------------------
extern "C" void kernel_launch(void* const* d_in, const int* in_sizes, int n_in,
                              void* d_out, int out_size) {
    const float* h     = (const float*)d_in[0];
    const void*  ei    = d_in[1];
    const float* W1    = (const float*)d_in[2];
    const float* b1    = (const float*)d_in[3];
    const float* W2    = (const float*)d_in[4];
    const float* b2    = (const float*)d_in[5];
    const float* gamma = (const float*)d_in[6];
    const float* beta  = (const float*)d_in[7];
    float*       out   = (float*)d_out;

    int N = in_sizes[0] / D;
    int E = in_sizes[1] / 2;
    int L = in_sizes[2] / (D * D);

    int n4 = N * (D / 4);
    int copyBlocks = (n4 + 255) / 256;
    long long scatThreads = (long long)E * 32;
    int scatBlocks = (int)((scatThreads + 255) / 256);
    int gemmBlocks = (N + 127) / 128;

    probe_idx_type<<<1, 1>>>(ei, E, N);

    for (int l = 0; l < L; ++l) {
        const float* x = (l == 0) ? h : out + (size_t)(l - 1) * N * D;
        float* y = out + (size_t)l * N * D;

        copy_init<<<copyBlocks, 256>>>((const float4*)x, n4);
        scatter_add<<<scatBlocks, 256>>>((const float4*)x, ei, E, N);
        gemm_bias_act<1><<<gemmBlocks, 256>>>(W1 + (size_t)l * D * D, b1 + l * D, N, 1);
        gemm_bias_act<0><<<gemmBlocks, 256>>>(W2 + (size_t)l * D * D, b2 + l * D, N, 0);
        zero_stats<<<1, 2 * D>>>();
        col_stats<<<392, 256>>>(N);
        bn_finalize<<<1, D>>>(gamma + l * D, beta + l * D, 1.0f / (float)N);
        bn_relu<<<copyBlocks, 256>>>((float4*)y, n4);
    }
}

// round 4
// speedup vs baseline: 1.0864x; 1.0864x over previous
#include <cuda_runtime.h>
#include <cstdint>

#define D 128
#define MAXN 50000

// Scratch (no allocations allowed in kernel_launch).
__device__ __align__(16) float g_z[(size_t)MAXN * D];   // z = x + agg, later z2
__device__ __align__(16) float g_h[(size_t)MAXN * D];   // hidden
__device__ __align__(16) float g_stats[2 * D];          // col sum, col sumsq
__device__ __align__(16) float g_scale[D];
__device__ __align__(16) float g_shift[D];
__device__ int g_idx_is64;

// ---------------------------------------------------------------------------
__global__ void probe_idx_type(const void* ei, int E, int N) {
    const long long* p = (const long long*)ei;
    int n = E < 64 ? E : 64;
    int ok = 1;
    for (int i = 0; i < n; ++i) {
        long long v = p[i];
        if (v < 0 || v >= N) { ok = 0; break; }
    }
    g_idx_is64 = ok;
}

__global__ void copy_init(const float4* __restrict__ x, int n4) {
    int i = blockIdx.x * blockDim.x + threadIdx.x;
    if (i < n4) reinterpret_cast<float4*>(g_z)[i] = x[i];
}

__global__ void scatter_add(const float4* __restrict__ x,
                            const void* __restrict__ ei,
                            int E, int N) {
    int w = (blockIdx.x * blockDim.x + threadIdx.x) >> 5;
    int lane = threadIdx.x & 31;
    if (w >= E) return;
    int s, d;
    if (g_idx_is64) {
        const long long* p = (const long long*)ei;
        s = (int)__ldg(&p[w]);
        d = (int)__ldg(&p[E + w]);
    } else {
        const int* p = (const int*)ei;
        s = __ldg(&p[w]);
        d = __ldg(&p[E + w]);
    }
    if ((unsigned)s >= (unsigned)N || (unsigned)d >= (unsigned)N) return;
    float4 v = x[(size_t)s * (D / 4) + lane];
    atomicAdd(reinterpret_cast<float4*>(g_z) + (size_t)d * (D / 4) + lane, v);
}

// ---------------------------------------------------------------------------
// Tensor-core GEMM: C[N,128] = act(A[N,128] @ W[128,128] + bias)
// 3xTF32 split for fp32-level accuracy. Block 128x128, 8 warps (4 row x 2 col),
// warp tile 32x64 (2 m16 tiles x 8 n8 tiles). Optional fused BN column stats.
// FIRST=1: A=g_z, C=g_h, relu. FIRST=0: A=g_h, C=g_z, stats.
// ---------------------------------------------------------------------------
__device__ __forceinline__ void split_tf32(float x, uint32_t& hi, uint32_t& lo) {
    uint32_t h;
    asm("cvt.rna.tf32.f32 %0, %1;" : "=r"(h) : "f"(x));
    float r = x - __uint_as_float(h);
    uint32_t l;
    asm("cvt.rna.tf32.f32 %0, %1;" : "=r"(l) : "f"(r));
    hi = h; lo = l;
}

__device__ __forceinline__ void mma_tf32(float c[4], const uint32_t a[4], const uint32_t b[2]) {
    asm volatile(
        "mma.sync.aligned.m16n8k8.row.col.f32.tf32.tf32.f32 "
        "{%0,%1,%2,%3}, {%4,%5,%6,%7}, {%8,%9}, {%0,%1,%2,%3};"
        : "+f"(c[0]), "+f"(c[1]), "+f"(c[2]), "+f"(c[3])
        : "r"(a[0]), "r"(a[1]), "r"(a[2]), "r"(a[3]), "r"(b[0]), "r"(b[1]));
}

template <int FIRST>
__global__ __launch_bounds__(256) void gemm_tc(
    const float* __restrict__ W, const float* __restrict__ bias, int N) {
    const float* __restrict__ A = FIRST ? g_z : g_h;
    float* __restrict__ C = FIRST ? g_h : g_z;

    __shared__ float As[128][20];   // [row][k], stride 20: frag reads conflict-free
    __shared__ float Bs[16][136];   // [k][n],  stride 136: frag reads conflict-free

    int tid = threadIdx.x;
    int warp = tid >> 5, lane = tid & 31;
    int wr = warp >> 1;         // 0..3
    int wc = warp & 1;          // 0..1
    int rowBase = blockIdx.x * 128;
    int lq = lane & 3;          // thread-in-group (k)
    int lg = lane >> 2;         // group id (row / col)

    float acc[2][8][4] = {};

    for (int k0 = 0; k0 < D; k0 += 16) {
        // stage A: 128 rows x 16 k = 512 float4s, 2 per thread
#pragma unroll
        for (int it = 0; it < 2; ++it) {
            int i = tid + it * 256;
            int row = rowBase + (i >> 2);
            int gr = row < N ? row : N - 1;
            float4 v = *reinterpret_cast<const float4*>(A + (size_t)gr * D + k0 + (i & 3) * 4);
            *reinterpret_cast<float4*>(&As[i >> 2][(i & 3) * 4]) = v;
        }
        // stage B: 16 k x 128 n = 512 float4s, 2 per thread
#pragma unroll
        for (int it = 0; it < 2; ++it) {
            int i = tid + it * 256;
            int row = i >> 5, c4 = (i & 31) * 4;
            *reinterpret_cast<float4*>(&Bs[row][c4]) =
                *reinterpret_cast<const float4*>(W + (size_t)(k0 + row) * D + c4);
        }
        __syncthreads();

#pragma unroll
        for (int ks = 0; ks < 2; ++ks) {
            int kb = ks * 8;
            uint32_t ah[2][4], al[2][4];
#pragma unroll
            for (int mt = 0; mt < 2; ++mt) {
                int r0 = wr * 32 + mt * 16 + lg;
                int kk = kb + lq;
                split_tf32(As[r0][kk],         ah[mt][0], al[mt][0]);
                split_tf32(As[r0 + 8][kk],     ah[mt][1], al[mt][1]);
                split_tf32(As[r0][kk + 4],     ah[mt][2], al[mt][2]);
                split_tf32(As[r0 + 8][kk + 4], ah[mt][3], al[mt][3]);
            }
#pragma unroll
            for (int nt = 0; nt < 8; ++nt) {
                int n0 = wc * 64 + nt * 8 + lg;
                int kk = kb + lq;
                uint32_t bh[2], bl[2];
                split_tf32(Bs[kk][n0],     bh[0], bl[0]);
                split_tf32(Bs[kk + 4][n0], bh[1], bl[1]);
#pragma unroll
                for (int mt = 0; mt < 2; ++mt) {
                    mma_tf32(acc[mt][nt], ah[mt], bh);
                    mma_tf32(acc[mt][nt], al[mt], bh);
                    mma_tf32(acc[mt][nt], ah[mt], bl);
                }
            }
        }
        __syncthreads();
    }

    // Epilogue: bias (+relu for FIRST) store; fused BN stats for !FIRST.
#pragma unroll
    for (int nt = 0; nt < 8; ++nt) {
        int col = wc * 64 + nt * 8 + 2 * lq;
        float b0 = bias[col], b1 = bias[col + 1];
        float s0 = 0.f, s1 = 0.f, q0 = 0.f, q1 = 0.f;
#pragma unroll
        for (int mt = 0; mt < 2; ++mt) {
            int r0 = rowBase + wr * 32 + mt * 16 + lg;
            int r1 = r0 + 8;
            float v00 = acc[mt][nt][0] + b0;
            float v01 = acc[mt][nt][1] + b1;
            float v10 = acc[mt][nt][2] + b0;
            float v11 = acc[mt][nt][3] + b1;
            if (FIRST) {
                v00 = fmaxf(v00, 0.f); v01 = fmaxf(v01, 0.f);
                v10 = fmaxf(v10, 0.f); v11 = fmaxf(v11, 0.f);
            }
            if (r0 < N) {
                *reinterpret_cast<float2*>(C + (size_t)r0 * D + col) = make_float2(v00, v01);
                if (!FIRST) { s0 += v00; s1 += v01; q0 += v00 * v00; q1 += v01 * v01; }
            }
            if (r1 < N) {
                *reinterpret_cast<float2*>(C + (size_t)r1 * D + col) = make_float2(v10, v11);
                if (!FIRST) { s0 += v10; s1 += v11; q0 += v10 * v10; q1 += v11 * v11; }
            }
        }
        if (!FIRST) {
            // reduce over the 8 row-groups (lanes differing in lg bits)
#pragma unroll
            for (int m = 4; m <= 16; m <<= 1) {
                s0 += __shfl_xor_sync(0xffffffffu, s0, m);
                s1 += __shfl_xor_sync(0xffffffffu, s1, m);
                q0 += __shfl_xor_sync(0xffffffffu, q0, m);
                q1 += __shfl_xor_sync(0xffffffffu, q1, m);
            }
            if (lg == 0) {
                atomicAdd(&g_stats[col], s0);
                atomicAdd(&g_stats[col + 1], s1);
                atomicAdd(&g_stats[D + col], q0);
                atomicAdd(&g_stats[D + col + 1], q1);
            }
        }
    }
}

// ---------------------------------------------------------------------------
__global__ void zero_stats() {
    g_stats[threadIdx.x] = 0.f;
}

__global__ void bn_finalize(const float* __restrict__ gamma,
                            const float* __restrict__ beta, float invN) {
    int c = threadIdx.x;
    float s = g_stats[c], q = g_stats[D + c];
    float mean = s * invN;
    float var = fmaxf(q * invN - mean * mean, 0.f);
    float a = gamma[c] * rsqrtf(var + 1e-5f);
    g_scale[c] = a;
    g_shift[c] = beta[c] - mean * a;
}

__global__ void bn_relu(float4* __restrict__ y, int n4) {
    int i = blockIdx.x * blockDim.x + threadIdx.x;
    if (i >= n4) return;
    int c = i & (D / 4 - 1);
    float4 a = *reinterpret_cast<const float4*>(&g_scale[c * 4]);
    float4 b = *reinterpret_cast<const float4*>(&g_shift[c * 4]);
    float4 v = reinterpret_cast<const float4*>(g_z)[i];
    v.x = fmaxf(v.x * a.x + b.x, 0.f);
    v.y = fmaxf(v.y * a.y + b.y, 0.f);
    v.z = fmaxf(v.z * a.z + b.z, 0.f);
    v.w = fmaxf(v.w * a.w + b.w, 0.f);
    y[i] = v;
}

// ---------------------------------------------------------------------------
extern "C" void kernel_launch(void* const* d_in, const int* in_sizes, int n_in,
                              void* d_out, int out_size) {
    const float* h     = (const float*)d_in[0];
    const void*  ei    = d_in[1];
    const float* W1    = (const float*)d_in[2];
    const float* b1    = (const float*)d_in[3];
    const float* W2    = (const float*)d_in[4];
    const float* b2    = (const float*)d_in[5];
    const float* gamma = (const float*)d_in[6];
    const float* beta  = (const float*)d_in[7];
    float*       out   = (float*)d_out;

    int N = in_sizes[0] / D;
    int E = in_sizes[1] / 2;
    int L = in_sizes[2] / (D * D);

    int n4 = N * (D / 4);
    int copyBlocks = (n4 + 255) / 256;
    long long scatThreads = (long long)E * 32;
    int scatBlocks = (int)((scatThreads + 255) / 256);
    int gemmBlocks = (N + 127) / 128;

    probe_idx_type<<<1, 1>>>(ei, E, N);

    for (int l = 0; l < L; ++l) {
        const float* x = (l == 0) ? h : out + (size_t)(l - 1) * N * D;
        float* y = out + (size_t)l * N * D;

        copy_init<<<copyBlocks, 256>>>((const float4*)x, n4);
        scatter_add<<<scatBlocks, 256>>>((const float4*)x, ei, E, N);
        gemm_tc<1><<<gemmBlocks, 256>>>(W1 + (size_t)l * D * D, b1 + l * D, N);
        zero_stats<<<1, 2 * D>>>();
        gemm_tc<0><<<gemmBlocks, 256>>>(W2 + (size_t)l * D * D, b2 + l * D, N);
        bn_finalize<<<1, D>>>(gamma + l * D, beta + l * D, 1.0f / (float)N);
        bn_relu<<<copyBlocks, 256>>>((float4*)y, n4);
    }
}

// round 5
// speedup vs baseline: 1.1463x; 1.0551x over previous
#include <cuda_runtime.h>
#include <cstdint>

#define D 128
#define MAXN 50000
#define MAXE 800000

// Scratch (no allocations allowed in kernel_launch).
__device__ __align__(16) float g_z[(size_t)MAXN * D];   // z = x + agg, later z2
__device__ __align__(16) float g_h[(size_t)MAXN * D];   // hidden
__device__ __align__(16) float g_stats[2 * D];          // col sum, col sumsq
__device__ __align__(16) float g_scale[D];
__device__ __align__(16) float g_shift[D];
__device__ __align__(16) uint32_t g_WH[D * D];          // tf32 hi of current W
__device__ __align__(16) uint32_t g_WL[D * D];          // tf32 lo of current W
__device__ int g_idx_is64;
// CSR of in-edges (built once per call; edge list is constant across layers)
__device__ int g_deg[MAXN];
__device__ int g_row_ptr[MAXN + 1];
__device__ int g_cursor[MAXN];
__device__ int g_esrc[MAXE];

// ---------------------------------------------------------------------------
__global__ void probe_idx_type(const void* ei, int E, int N) {
    const long long* p = (const long long*)ei;
    int n = E < 64 ? E : 64;
    int ok = 1;
    for (int i = 0; i < n; ++i) {
        long long v = p[i];
        if (v < 0 || v >= N) { ok = 0; break; }
    }
    g_idx_is64 = ok;
}

__device__ __forceinline__ int load_idx(const void* ei, int i) {
    if (g_idx_is64) return (int)__ldg(&((const long long*)ei)[i]);
    return __ldg(&((const int*)ei)[i]);
}

// ---------------------------------------------------------------------------
// CSR build: zero degrees -> histogram over dst -> exclusive scan -> fill
// ---------------------------------------------------------------------------
__global__ void zero_deg(int N) {
    int i = blockIdx.x * blockDim.x + threadIdx.x;
    if (i < N) g_deg[i] = 0;
}

__global__ void hist_dst(const void* ei, int E, int N) {
    int i = blockIdx.x * blockDim.x + threadIdx.x;
    if (i >= E) return;
    int d = load_idx(ei, E + i);
    if ((unsigned)d < (unsigned)N) atomicAdd(&g_deg[d], 1);
}

__global__ void scan_deg(int N) {
    __shared__ int sh[1024];
    int tid = threadIdx.x;
    int chunk = (N + 1023) / 1024;
    int start = min(tid * chunk, N);
    int end = min(start + chunk, N);
    int s = 0;
    for (int i = start; i < end; ++i) s += g_deg[i];
    sh[tid] = s;
    __syncthreads();
    // Hillis-Steele inclusive scan
    for (int off = 1; off < 1024; off <<= 1) {
        int v = (tid >= off) ? sh[tid - off] : 0;
        __syncthreads();
        sh[tid] += v;
        __syncthreads();
    }
    int run = sh[tid] - s;  // exclusive prefix
    for (int i = start; i < end; ++i) {
        int d = g_deg[i];
        g_row_ptr[i] = run;
        g_cursor[i] = run;
        run += d;
    }
    if (end == N) g_row_ptr[N] = run;
}

__global__ void fill_csr(const void* ei, int E, int N) {
    int i = blockIdx.x * blockDim.x + threadIdx.x;
    if (i >= E) return;
    int s = load_idx(ei, i);
    int d = load_idx(ei, E + i);
    if ((unsigned)s >= (unsigned)N || (unsigned)d >= (unsigned)N) return;
    int pos = atomicAdd(&g_cursor[d], 1);
    g_esrc[pos] = s;
}

// ---------------------------------------------------------------------------
// Aggregation: one warp per node. z[node] = x[node] + sum_{e in in(node)} x[src_e]
// Lane covers one float4 (D/4 == 32 == warp size). No atomics, coalesced I/O.
// ---------------------------------------------------------------------------
__global__ void aggregate(const float4* __restrict__ x, int N) {
    int node = (blockIdx.x * blockDim.x + threadIdx.x) >> 5;
    int lane = threadIdx.x & 31;
    if (node >= N) return;
    float4 acc = x[(size_t)node * 32 + lane];
    int e = g_row_ptr[node], end = g_row_ptr[node + 1];
    for (; e + 3 < end; e += 4) {
        int s0 = __ldg(&g_esrc[e]);
        int s1 = __ldg(&g_esrc[e + 1]);
        int s2 = __ldg(&g_esrc[e + 2]);
        int s3 = __ldg(&g_esrc[e + 3]);
        float4 v0 = x[(size_t)s0 * 32 + lane];
        float4 v1 = x[(size_t)s1 * 32 + lane];
        float4 v2 = x[(size_t)s2 * 32 + lane];
        float4 v3 = x[(size_t)s3 * 32 + lane];
        acc.x += v0.x + v1.x + v2.x + v3.x;
        acc.y += v0.y + v1.y + v2.y + v3.y;
        acc.z += v0.z + v1.z + v2.z + v3.z;
        acc.w += v0.w + v1.w + v2.w + v3.w;
    }
    for (; e < end; ++e) {
        int s = __ldg(&g_esrc[e]);
        float4 v = x[(size_t)s * 32 + lane];
        acc.x += v.x; acc.y += v.y; acc.z += v.z; acc.w += v.w;
    }
    reinterpret_cast<float4*>(g_z)[(size_t)node * 32 + lane] = acc;
}

// ---------------------------------------------------------------------------
// tf32 split helpers + weight pre-split
// ---------------------------------------------------------------------------
__device__ __forceinline__ void split_tf32(float x, uint32_t& hi, uint32_t& lo) {
    uint32_t h;
    asm("cvt.rna.tf32.f32 %0, %1;" : "=r"(h) : "f"(x));
    float r = x - __uint_as_float(h);
    uint32_t l;
    asm("cvt.rna.tf32.f32 %0, %1;" : "=r"(l) : "f"(r));
    hi = h; lo = l;
}

__global__ void split_w(const float* __restrict__ W) {
    int i = blockIdx.x * blockDim.x + threadIdx.x;
    if (i < D * D) {
        uint32_t h, l;
        split_tf32(W[i], h, l);
        g_WH[i] = h; g_WL[i] = l;
    }
}

__device__ __forceinline__ void mma_tf32(float c[4], const uint32_t a[4], const uint32_t b[2]) {
    asm volatile(
        "mma.sync.aligned.m16n8k8.row.col.f32.tf32.tf32.f32 "
        "{%0,%1,%2,%3}, {%4,%5,%6,%7}, {%8,%9}, {%0,%1,%2,%3};"
        : "+f"(c[0]), "+f"(c[1]), "+f"(c[2]), "+f"(c[3])
        : "r"(a[0]), "r"(a[1]), "r"(a[2]), "r"(a[3]), "r"(b[0]), "r"(b[1]));
}

// ---------------------------------------------------------------------------
// Tensor-core GEMM, 3xTF32, splits hoisted to staging / pre-split weights.
// Block 128x128, 8 warps (4 row x 2 col), warp tile 32x64.
// FIRST=1: A=g_z, C=g_h, relu. FIRST=0: A=g_h, C=g_z, fused BN stats.
// ---------------------------------------------------------------------------
template <int FIRST>
__global__ __launch_bounds__(256) void gemm_tc(const float* __restrict__ bias, int N) {
    const float* __restrict__ A = FIRST ? g_z : g_h;
    float* __restrict__ C = FIRST ? g_h : g_z;

    __shared__ uint32_t AsH[128][20], AsL[128][20];   // [row][k], pad 20
    __shared__ uint32_t BsH[16][136], BsL[16][136];   // [k][n],  pad 136

    int tid = threadIdx.x;
    int warp = tid >> 5, lane = tid & 31;
    int wr = warp >> 1;         // 0..3
    int wc = warp & 1;          // 0..1
    int rowBase = blockIdx.x * 128;
    int lq = lane & 3;          // k within group
    int lg = lane >> 2;         // row/col group

    float acc[2][8][4] = {};

    for (int k0 = 0; k0 < D; k0 += 16) {
        // stage A: 128 rows x 16 k; split once per element here
#pragma unroll
        for (int it = 0; it < 2; ++it) {
            int i = tid + it * 256;
            int row = rowBase + (i >> 2);
            int gr = row < N ? row : N - 1;
            float4 v = *reinterpret_cast<const float4*>(A + (size_t)gr * D + k0 + (i & 3) * 4);
            int r = i >> 2, c = (i & 3) * 4;
            uint32_t h, l;
            split_tf32(v.x, h, l); AsH[r][c + 0] = h; AsL[r][c + 0] = l;
            split_tf32(v.y, h, l); AsH[r][c + 1] = h; AsL[r][c + 1] = l;
            split_tf32(v.z, h, l); AsH[r][c + 2] = h; AsL[r][c + 2] = l;
            split_tf32(v.w, h, l); AsH[r][c + 3] = h; AsL[r][c + 3] = l;
        }
        // stage B: pre-split weights, no cvt
#pragma unroll
        for (int it = 0; it < 2; ++it) {
            int i = tid + it * 256;
            int row = i >> 5, c4 = (i & 31) * 4;
            *reinterpret_cast<uint4*>(&BsH[row][c4]) =
                *reinterpret_cast<const uint4*>(&g_WH[(size_t)(k0 + row) * D + c4]);
            *reinterpret_cast<uint4*>(&BsL[row][c4]) =
                *reinterpret_cast<const uint4*>(&g_WL[(size_t)(k0 + row) * D + c4]);
        }
        __syncthreads();

#pragma unroll
        for (int ks = 0; ks < 2; ++ks) {
            int kb = ks * 8;
            uint32_t ah[2][4], al[2][4];
#pragma unroll
            for (int mt = 0; mt < 2; ++mt) {
                int r0 = wr * 32 + mt * 16 + lg;
                int kk = kb + lq;
                ah[mt][0] = AsH[r0][kk];         al[mt][0] = AsL[r0][kk];
                ah[mt][1] = AsH[r0 + 8][kk];     al[mt][1] = AsL[r0 + 8][kk];
                ah[mt][2] = AsH[r0][kk + 4];     al[mt][2] = AsL[r0][kk + 4];
                ah[mt][3] = AsH[r0 + 8][kk + 4]; al[mt][3] = AsL[r0 + 8][kk + 4];
            }
#pragma unroll
            for (int nt = 0; nt < 8; ++nt) {
                int n0 = wc * 64 + nt * 8 + lg;
                int kk = kb + lq;
                uint32_t bh[2], bl[2];
                bh[0] = BsH[kk][n0];     bl[0] = BsL[kk][n0];
                bh[1] = BsH[kk + 4][n0]; bl[1] = BsL[kk + 4][n0];
#pragma unroll
                for (int mt = 0; mt < 2; ++mt) {
                    mma_tf32(acc[mt][nt], ah[mt], bh);
                    mma_tf32(acc[mt][nt], al[mt], bh);
                    mma_tf32(acc[mt][nt], ah[mt], bl);
                }
            }
        }
        __syncthreads();
    }

    // Epilogue: bias (+relu for FIRST) store; fused BN stats for !FIRST.
#pragma unroll
    for (int nt = 0; nt < 8; ++nt) {
        int col = wc * 64 + nt * 8 + 2 * lq;
        float b0 = bias[col], b1 = bias[col + 1];
        float s0 = 0.f, s1 = 0.f, q0 = 0.f, q1 = 0.f;
#pragma unroll
        for (int mt = 0; mt < 2; ++mt) {
            int r0 = rowBase + wr * 32 + mt * 16 + lg;
            int r1 = r0 + 8;
            float v00 = acc[mt][nt][0] + b0;
            float v01 = acc[mt][nt][1] + b1;
            float v10 = acc[mt][nt][2] + b0;
            float v11 = acc[mt][nt][3] + b1;
            if (FIRST) {
                v00 = fmaxf(v00, 0.f); v01 = fmaxf(v01, 0.f);
                v10 = fmaxf(v10, 0.f); v11 = fmaxf(v11, 0.f);
            }
            if (r0 < N) {
                *reinterpret_cast<float2*>(C + (size_t)r0 * D + col) = make_float2(v00, v01);
                if (!FIRST) { s0 += v00; s1 += v01; q0 += v00 * v00; q1 += v01 * v01; }
            }
            if (r1 < N) {
                *reinterpret_cast<float2*>(C + (size_t)r1 * D + col) = make_float2(v10, v11);
                if (!FIRST) { s0 += v10; s1 += v11; q0 += v10 * v10; q1 += v11 * v11; }
            }
        }
        if (!FIRST) {
#pragma unroll
            for (int m = 4; m <= 16; m <<= 1) {
                s0 += __shfl_xor_sync(0xffffffffu, s0, m);
                s1 += __shfl_xor_sync(0xffffffffu, s1, m);
                q0 += __shfl_xor_sync(0xffffffffu, q0, m);
                q1 += __shfl_xor_sync(0xffffffffu, q1, m);
            }
            if (lg == 0) {
                atomicAdd(&g_stats[col], s0);
                atomicAdd(&g_stats[col + 1], s1);
                atomicAdd(&g_stats[D + col], q0);
                atomicAdd(&g_stats[D + col + 1], q1);
            }
        }
    }
}

// ---------------------------------------------------------------------------
__global__ void zero_stats() {
    g_stats[threadIdx.x] = 0.f;
}

__global__ void bn_finalize(const float* __restrict__ gamma,
                            const float* __restrict__ beta, float invN) {
    int c = threadIdx.x;
    float s = g_stats[c], q = g_stats[D + c];
    float mean = s * invN;
    float var = fmaxf(q * invN - mean * mean, 0.f);
    float a = gamma[c] * rsqrtf(var + 1e-5f);
    g_scale[c] = a;
    g_shift[c] = beta[c] - mean * a;
}

__global__ void bn_relu(float4* __restrict__ y, int n4) {
    int i = blockIdx.x * blockDim.x + threadIdx.x;
    if (i >= n4) return;
    int c = i & (D / 4 - 1);
    float4 a = *reinterpret_cast<const float4*>(&g_scale[c * 4]);
    float4 b = *reinterpret_cast<const float4*>(&g_shift[c * 4]);
    float4 v = reinterpret_cast<const float4*>(g_z)[i];
    v.x = fmaxf(v.x * a.x + b.x, 0.f);
    v.y = fmaxf(v.y * a.y + b.y, 0.f);
    v.z = fmaxf(v.z * a.z + b.z, 0.f);
    v.w = fmaxf(v.w * a.w + b.w, 0.f);
    y[i] = v;
}

// ---------------------------------------------------------------------------
extern "C" void kernel_launch(void* const* d_in, const int* in_sizes, int n_in,
                              void* d_out, int out_size) {
    const float* h     = (const float*)d_in[0];
    const void*  ei    = d_in[1];
    const float* W1    = (const float*)d_in[2];
    const float* b1    = (const float*)d_in[3];
    const float* W2    = (const float*)d_in[4];
    const float* b2    = (const float*)d_in[5];
    const float* gamma = (const float*)d_in[6];
    const float* beta  = (const float*)d_in[7];
    float*       out   = (float*)d_out;

    int N = in_sizes[0] / D;
    int E = in_sizes[1] / 2;
    int L = in_sizes[2] / (D * D);

    int n4 = N * (D / 4);
    int vecBlocks = (n4 + 255) / 256;
    int eBlocks = (E + 255) / 256;
    int nBlocks = (N + 255) / 256;
    int aggBlocks = (N * 32 + 255) / 256;
    int gemmBlocks = (N + 127) / 128;

    probe_idx_type<<<1, 1>>>(ei, E, N);
    // Build in-edge CSR once (edge list is layer-invariant)
    zero_deg<<<nBlocks, 256>>>(N);
    hist_dst<<<eBlocks, 256>>>(ei, E, N);
    scan_deg<<<1, 1024>>>(N);
    fill_csr<<<eBlocks, 256>>>(ei, E, N);

    for (int l = 0; l < L; ++l) {
        const float* x = (l == 0) ? h : out + (size_t)(l - 1) * N * D;
        float* y = out + (size_t)l * N * D;

        aggregate<<<aggBlocks, 256>>>((const float4*)x, N);
        split_w<<<(D * D + 255) / 256, 256>>>(W1 + (size_t)l * D * D);
        gemm_tc<1><<<gemmBlocks, 256>>>(b1 + l * D, N);
        zero_stats<<<1, 2 * D>>>();
        split_w<<<(D * D + 255) / 256, 256>>>(W2 + (size_t)l * D * D);
        gemm_tc<0><<<gemmBlocks, 256>>>(b2 + l * D, N);
        bn_finalize<<<1, D>>>(gamma + l * D, beta + l * D, 1.0f / (float)N);
        bn_relu<<<vecBlocks, 256>>>((float4*)y, n4);
    }
}

// round 7
// speedup vs baseline: 1.3870x; 1.2100x over previous
#include <cuda_runtime.h>
#include <cstdint>

#define D 128
#define MAXN 50000
#define MAXE 800000
#define SCAN_TILE 2048          // elements per scan block
#define MAX_SCAN_BLOCKS 256

// Scratch (no allocations allowed in kernel_launch).
__device__ __align__(16) float g_z[(size_t)MAXN * D];   // z = x + agg, later z2
__device__ __align__(16) float g_h[(size_t)MAXN * D];   // hidden
__device__ __align__(16) float g_stats[2 * D];          // col sum, col sumsq
__device__ __align__(16) float g_scale[D];
__device__ __align__(16) float g_shift[D];
__device__ __align__(16) uint32_t g_WH[D * D];          // tf32 hi of current W
__device__ __align__(16) uint32_t g_WL[D * D];          // tf32 lo of current W
__device__ int g_idx_is64;
// CSR of in-edges (built once per call; edge list is constant across layers)
__device__ int g_deg[MAXN];
__device__ int g_row_ptr[MAXN + 1];
__device__ int g_cursor[MAXN];
__device__ int g_esrc[MAXE];
__device__ int g_bsum[MAX_SCAN_BLOCKS];
__device__ int g_bpre[MAX_SCAN_BLOCKS];

// ---------------------------------------------------------------------------
__global__ void probe_idx_type(const void* ei, int E, int N) {
    const long long* p = (const long long*)ei;
    int n = E < 64 ? E : 64;
    int ok = 1;
    for (int i = 0; i < n; ++i) {
        long long v = p[i];
        if (v < 0 || v >= N) { ok = 0; break; }
    }
    g_idx_is64 = ok;
}

__device__ __forceinline__ int load_idx(const void* ei, int i) {
    if (g_idx_is64) return (int)__ldg(&((const long long*)ei)[i]);
    return __ldg(&((const int*)ei)[i]);
}

// ---------------------------------------------------------------------------
// CSR build: zero -> histogram -> 3-phase parallel scan -> fill
// ---------------------------------------------------------------------------
__global__ void zero_deg(int N) {
    int i = blockIdx.x * blockDim.x + threadIdx.x;
    if (i < N) g_deg[i] = 0;
}

__global__ void hist_dst(const void* ei, int E, int N) {
    int i = blockIdx.x * blockDim.x + threadIdx.x;
    if (i >= E) return;
    int d = load_idx(ei, E + i);
    if ((unsigned)d < (unsigned)N) atomicAdd(&g_deg[d], 1);
}

// Phase 1: per-block (2048-elem tile) sum of degrees
__global__ void scan_block_sum(int N) {
    __shared__ int sh[256];
    int base = blockIdx.x * SCAN_TILE;
    int s = 0;
#pragma unroll
    for (int it = 0; it < 8; ++it) {
        int i = base + it * 256 + threadIdx.x;
        if (i < N) s += g_deg[i];
    }
    sh[threadIdx.x] = s;
    __syncthreads();
    for (int off = 128; off > 0; off >>= 1) {
        if (threadIdx.x < off) sh[threadIdx.x] += sh[threadIdx.x + off];
        __syncthreads();
    }
    if (threadIdx.x == 0) g_bsum[blockIdx.x] = sh[0];
}

// Phase 2: single-block exclusive scan over block sums (nb <= 256)
__global__ void scan_bsums(int nb, int N) {
    __shared__ int sh[MAX_SCAN_BLOCKS];
    int v = (threadIdx.x < nb) ? g_bsum[threadIdx.x] : 0;
    sh[threadIdx.x] = v;
    __syncthreads();
    for (int off = 1; off < MAX_SCAN_BLOCKS; off <<= 1) {
        int t = (threadIdx.x >= off) ? sh[threadIdx.x - off] : 0;
        __syncthreads();
        sh[threadIdx.x] += t;
        __syncthreads();
    }
    if (threadIdx.x < nb) g_bpre[threadIdx.x] = sh[threadIdx.x] - v;
    if (threadIdx.x == nb - 1) g_row_ptr[N] = sh[threadIdx.x];
}

// Phase 3: within-tile exclusive scan + block offset -> row_ptr, cursor
__global__ void scan_write(int N) {
    __shared__ int sh[256];
    int base = blockIdx.x * SCAN_TILE;
    int tstart = base + threadIdx.x * 8;
    int local[8];
    int s = 0;
#pragma unroll
    for (int j = 0; j < 8; ++j) {
        int i = tstart + j;
        int d = (i < N) ? g_deg[i] : 0;
        local[j] = s;          // exclusive within thread
        s += d;
    }
    sh[threadIdx.x] = s;
    __syncthreads();
    for (int off = 1; off < 256; off <<= 1) {
        int t = (threadIdx.x >= off) ? sh[threadIdx.x - off] : 0;
        __syncthreads();
        sh[threadIdx.x] += t;
        __syncthreads();
    }
    int tpre = sh[threadIdx.x] - s + g_bpre[blockIdx.x];  // exclusive prefix of this thread's run
#pragma unroll
    for (int j = 0; j < 8; ++j) {
        int i = tstart + j;
        if (i < N) {
            int r = tpre + local[j];
            g_row_ptr[i] = r;
            g_cursor[i] = r;
        }
    }
}

__global__ void fill_csr(const void* ei, int E, int N) {
    int i = blockIdx.x * blockDim.x + threadIdx.x;
    if (i >= E) return;
    int s = load_idx(ei, i);
    int d = load_idx(ei, E + i);
    if ((unsigned)s >= (unsigned)N || (unsigned)d >= (unsigned)N) return;
    int pos = atomicAdd(&g_cursor[d], 1);
    g_esrc[pos] = s;
}

// ---------------------------------------------------------------------------
// Aggregation: one warp per node. z[node] = x[node] + sum_{e in in(node)} x[src_e]
// ---------------------------------------------------------------------------
__global__ void aggregate(const float4* __restrict__ x, int N) {
    int node = (blockIdx.x * blockDim.x + threadIdx.x) >> 5;
    int lane = threadIdx.x & 31;
    if (node >= N) return;
    float4 acc = x[(size_t)node * 32 + lane];
    int e = g_row_ptr[node], end = g_row_ptr[node + 1];
    for (; e + 3 < end; e += 4) {
        int s0 = __ldg(&g_esrc[e]);
        int s1 = __ldg(&g_esrc[e + 1]);
        int s2 = __ldg(&g_esrc[e + 2]);
        int s3 = __ldg(&g_esrc[e + 3]);
        float4 v0 = x[(size_t)s0 * 32 + lane];
        float4 v1 = x[(size_t)s1 * 32 + lane];
        float4 v2 = x[(size_t)s2 * 32 + lane];
        float4 v3 = x[(size_t)s3 * 32 + lane];
        acc.x += v0.x + v1.x + v2.x + v3.x;
        acc.y += v0.y + v1.y + v2.y + v3.y;
        acc.z += v0.z + v1.z + v2.z + v3.z;
        acc.w += v0.w + v1.w + v2.w + v3.w;
    }
    for (; e < end; ++e) {
        int s = __ldg(&g_esrc[e]);
        float4 v = x[(size_t)s * 32 + lane];
        acc.x += v.x; acc.y += v.y; acc.z += v.z; acc.w += v.w;
    }
    reinterpret_cast<float4*>(g_z)[(size_t)node * 32 + lane] = acc;
}

// ---------------------------------------------------------------------------
// tf32 split helpers + weight pre-split
// ---------------------------------------------------------------------------
__device__ __forceinline__ void split_tf32(float x, uint32_t& hi, uint32_t& lo) {
    uint32_t h;
    asm("cvt.rna.tf32.f32 %0, %1;" : "=r"(h) : "f"(x));
    float r = x - __uint_as_float(h);
    uint32_t l;
    asm("cvt.rna.tf32.f32 %0, %1;" : "=r"(l) : "f"(r));
    hi = h; lo = l;
}

__global__ void split_w(const float* __restrict__ W) {
    int i = blockIdx.x * blockDim.x + threadIdx.x;
    if (i < D * D) {
        uint32_t h, l;
        split_tf32(W[i], h, l);
        g_WH[i] = h; g_WL[i] = l;
    }
}

__device__ __forceinline__ void mma_tf32(float c[4], const uint32_t a[4], const uint32_t b[2]) {
    asm volatile(
        "mma.sync.aligned.m16n8k8.row.col.f32.tf32.tf32.f32 "
        "{%0,%1,%2,%3}, {%4,%5,%6,%7}, {%8,%9}, {%0,%1,%2,%3};"
        : "+f"(c[0]), "+f"(c[1]), "+f"(c[2]), "+f"(c[3])
        : "r"(a[0]), "r"(a[1]), "r"(a[2]), "r"(a[3]), "r"(b[0]), "r"(b[1]));
}

// ---------------------------------------------------------------------------
// Tensor-core GEMM, 3xTF32, splits hoisted. Block 128x128, 8 warps.
// FIRST=1: A=g_z, C=g_h, relu. FIRST=0: A=g_h, C=g_z, fused BN stats.
// ---------------------------------------------------------------------------
template <int FIRST>
__global__ __launch_bounds__(256) void gemm_tc(const float* __restrict__ bias, int N) {
    const float* __restrict__ A = FIRST ? g_z : g_h;
    float* __restrict__ C = FIRST ? g_h : g_z;

    __shared__ uint32_t AsH[128][20], AsL[128][20];
    __shared__ uint32_t BsH[16][136], BsL[16][136];

    int tid = threadIdx.x;
    int warp = tid >> 5, lane = tid & 31;
    int wr = warp >> 1;
    int wc = warp & 1;
    int rowBase = blockIdx.x * 128;
    int lq = lane & 3;
    int lg = lane >> 2;

    float acc[2][8][4] = {};

    for (int k0 = 0; k0 < D; k0 += 16) {
#pragma unroll
        for (int it = 0; it < 2; ++it) {
            int i = tid + it * 256;
            int row = rowBase + (i >> 2);
            int gr = row < N ? row : N - 1;
            float4 v = *reinterpret_cast<const float4*>(A + (size_t)gr * D + k0 + (i & 3) * 4);
            int r = i >> 2, c = (i & 3) * 4;
            uint32_t h, l;
            split_tf32(v.x, h, l); AsH[r][c + 0] = h; AsL[r][c + 0] = l;
            split_tf32(v.y, h, l); AsH[r][c + 1] = h; AsL[r][c + 1] = l;
            split_tf32(v.z, h, l); AsH[r][c + 2] = h; AsL[r][c + 2] = l;
            split_tf32(v.w, h, l); AsH[r][c + 3] = h; AsL[r][c + 3] = l;
        }
#pragma unroll
        for (int it = 0; it < 2; ++it) {
            int i = tid + it * 256;
            int row = i >> 5, c4 = (i & 31) * 4;
            *reinterpret_cast<uint4*>(&BsH[row][c4]) =
                *reinterpret_cast<const uint4*>(&g_WH[(size_t)(k0 + row) * D + c4]);
            *reinterpret_cast<uint4*>(&BsL[row][c4]) =
                *reinterpret_cast<const uint4*>(&g_WL[(size_t)(k0 + row) * D + c4]);
        }
        __syncthreads();

#pragma unroll
        for (int ks = 0; ks < 2; ++ks) {
            int kb = ks * 8;
            uint32_t ah[2][4], al[2][4];
#pragma unroll
            for (int mt = 0; mt < 2; ++mt) {
                int r0 = wr * 32 + mt * 16 + lg;
                int kk = kb + lq;
                ah[mt][0] = AsH[r0][kk];         al[mt][0] = AsL[r0][kk];
                ah[mt][1] = AsH[r0 + 8][kk];     al[mt][1] = AsL[r0 + 8][kk];
                ah[mt][2] = AsH[r0][kk + 4];     al[mt][2] = AsL[r0][kk + 4];
                ah[mt][3] = AsH[r0 + 8][kk + 4]; al[mt][3] = AsL[r0 + 8][kk + 4];
            }
#pragma unroll
            for (int nt = 0; nt < 8; ++nt) {
                int n0 = wc * 64 + nt * 8 + lg;
                int kk = kb + lq;
                uint32_t bh[2], bl[2];
                bh[0] = BsH[kk][n0];     bl[0] = BsL[kk][n0];
                bh[1] = BsH[kk + 4][n0]; bl[1] = BsL[kk + 4][n0];
#pragma unroll
                for (int mt = 0; mt < 2; ++mt) {
                    mma_tf32(acc[mt][nt], ah[mt], bh);
                    mma_tf32(acc[mt][nt], al[mt], bh);
                    mma_tf32(acc[mt][nt], ah[mt], bl);
                }
            }
        }
        __syncthreads();
    }

#pragma unroll
    for (int nt = 0; nt < 8; ++nt) {
        int col = wc * 64 + nt * 8 + 2 * lq;
        float b0 = bias[col], b1 = bias[col + 1];
        float s0 = 0.f, s1 = 0.f, q0 = 0.f, q1 = 0.f;
#pragma unroll
        for (int mt = 0; mt < 2; ++mt) {
            int r0 = rowBase + wr * 32 + mt * 16 + lg;
            int r1 = r0 + 8;
            float v00 = acc[mt][nt][0] + b0;
            float v01 = acc[mt][nt][1] + b1;
            float v10 = acc[mt][nt][2] + b0;
            float v11 = acc[mt][nt][3] + b1;
            if (FIRST) {
                v00 = fmaxf(v00, 0.f); v01 = fmaxf(v01, 0.f);
                v10 = fmaxf(v10, 0.f); v11 = fmaxf(v11, 0.f);
            }
            if (r0 < N) {
                *reinterpret_cast<float2*>(C + (size_t)r0 * D + col) = make_float2(v00, v01);
                if (!FIRST) { s0 += v00; s1 += v01; q0 += v00 * v00; q1 += v01 * v01; }
            }
            if (r1 < N) {
                *reinterpret_cast<float2*>(C + (size_t)r1 * D + col) = make_float2(v10, v11);
                if (!FIRST) { s0 += v10; s1 += v11; q0 += v10 * v10; q1 += v11 * v11; }
            }
        }
        if (!FIRST) {
#pragma unroll
            for (int m = 4; m <= 16; m <<= 1) {
                s0 += __shfl_xor_sync(0xffffffffu, s0, m);
                s1 += __shfl_xor_sync(0xffffffffu, s1, m);
                q0 += __shfl_xor_sync(0xffffffffu, q0, m);
                q1 += __shfl_xor_sync(0xffffffffu, q1, m);
            }
            if (lg == 0) {
                atomicAdd(&g_stats[col], s0);
                atomicAdd(&g_stats[col + 1], s1);
                atomicAdd(&g_stats[D + col], q0);
                atomicAdd(&g_stats[D + col + 1], q1);
            }
        }
    }
}

// ---------------------------------------------------------------------------
__global__ void zero_stats() {
    g_stats[threadIdx.x] = 0.f;
}

__global__ void bn_finalize(const float* __restrict__ gamma,
                            const float* __restrict__ beta, float invN) {
    int c = threadIdx.x;
    float s = g_stats[c], q = g_stats[D + c];
    float mean = s * invN;
    float var = fmaxf(q * invN - mean * mean, 0.f);
    float a = gamma[c] * rsqrtf(var + 1e-5f);
    g_scale[c] = a;
    g_shift[c] = beta[c] - mean * a;
}

__global__ void bn_relu(float4* __restrict__ y, int n4) {
    int i = blockIdx.x * blockDim.x + threadIdx.x;
    if (i >= n4) return;
    int c = i & (D / 4 - 1);
    float4 a = *reinterpret_cast<const float4*>(&g_scale[c * 4]);
    float4 b = *reinterpret_cast<const float4*>(&g_shift[c * 4]);
    float4 v = reinterpret_cast<const float4*>(g_z)[i];
    v.x = fmaxf(v.x * a.x + b.x, 0.f);
    v.y = fmaxf(v.y * a.y + b.y, 0.f);
    v.z = fmaxf(v.z * a.z + b.z, 0.f);
    v.w = fmaxf(v.w * a.w + b.w, 0.f);
    y[i] = v;
}

// ---------------------------------------------------------------------------
extern "C" void kernel_launch(void* const* d_in, const int* in_sizes, int n_in,
                              void* d_out, int out_size) {
    const float* h     = (const float*)d_in[0];
    const void*  ei    = d_in[1];
    const float* W1    = (const float*)d_in[2];
    const float* b1    = (const float*)d_in[3];
    const float* W2    = (const float*)d_in[4];
    const float* b2    = (const float*)d_in[5];
    const float* gamma = (const float*)d_in[6];
    const float* beta  = (const float*)d_in[7];
    float*       out   = (float*)d_out;

    int N = in_sizes[0] / D;
    int E = in_sizes[1] / 2;
    int L = in_sizes[2] / (D * D);

    int n4 = N * (D / 4);
    int vecBlocks = (n4 + 255) / 256;
    int eBlocks = (E + 255) / 256;
    int nBlocks = (N + 255) / 256;
    int aggBlocks = (N * 32 + 255) / 256;
    int gemmBlocks = (N + 127) / 128;
    int scanBlocks = (N + SCAN_TILE - 1) / SCAN_TILE;

    probe_idx_type<<<1, 1>>>(ei, E, N);
    // Build in-edge CSR once (edge list is layer-invariant)
    zero_deg<<<nBlocks, 256>>>(N);
    hist_dst<<<eBlocks, 256>>>(ei, E, N);
    scan_block_sum<<<scanBlocks, 256>>>(N);
    scan_bsums<<<1, MAX_SCAN_BLOCKS>>>(scanBlocks, N);
    scan_write<<<scanBlocks, 256>>>(N);
    fill_csr<<<eBlocks, 256>>>(ei, E, N);

    for (int l = 0; l < L; ++l) {
        const float* x = (l == 0) ? h : out + (size_t)(l - 1) * N * D;
        float* y = out + (size_t)l * N * D;

        aggregate<<<aggBlocks, 256>>>((const float4*)x, N);
        split_w<<<(D * D + 255) / 256, 256>>>(W1 + (size_t)l * D * D);
        gemm_tc<1><<<gemmBlocks, 256>>>(b1 + l * D, N);
        zero_stats<<<1, 2 * D>>>();
        split_w<<<(D * D + 255) / 256, 256>>>(W2 + (size_t)l * D * D);
        gemm_tc<0><<<gemmBlocks, 256>>>(b2 + l * D, N);
        bn_finalize<<<1, D>>>(gamma + l * D, beta + l * D, 1.0f / (float)N);
        bn_relu<<<vecBlocks, 256>>>((float4*)y, n4);
    }
}

// round 8
// speedup vs baseline: 1.5033x; 1.0839x over previous
#include <cuda_runtime.h>
#include <cstdint>

#define D 128
#define MAXN 50000
#define MAXE 800000
#define MAXL 8
#define SCAN_TILE 2048
#define MAX_SCAN_BLOCKS 256

// Scratch (no allocations allowed in kernel_launch).
__device__ __align__(16) float g_z[(size_t)MAXN * D];
__device__ __align__(16) float g_h[(size_t)MAXN * D];
__device__ __align__(16) float g_stats[2 * D];          // col sum, col sumsq
__device__ __align__(16) float g_scale[D];
__device__ __align__(16) float g_shift[D];
__device__ __align__(16) uint32_t g_WH[2 * MAXL * D * D];  // tf32 hi: [which][layer]
__device__ __align__(16) uint32_t g_WL[2 * MAXL * D * D];  // tf32 lo
__device__ int g_idx_is64;
// CSR of in-edges (edge list is constant across layers)
__device__ int g_deg[MAXN];
__device__ int g_row_ptr[MAXN + 1];
__device__ int g_cursor[MAXN];
__device__ int g_esrc[MAXE];
__device__ int g_bsum[MAX_SCAN_BLOCKS];
__device__ int g_bpre[MAX_SCAN_BLOCKS];

// ---------------------------------------------------------------------------
__device__ __forceinline__ int load_idx(const void* ei, int i) {
    if (g_idx_is64) return (int)__ldg(&((const long long*)ei)[i]);
    return __ldg(&((const int*)ei)[i]);
}

// zero degrees + (block 0, thread 0) dtype probe
__global__ void zero_deg_probe(const void* ei, int E, int N) {
    int i = blockIdx.x * blockDim.x + threadIdx.x;
    if (i < N) g_deg[i] = 0;
    if (blockIdx.x == 0 && threadIdx.x == 0) {
        const long long* p = (const long long*)ei;
        int n = E < 64 ? E : 64;
        int ok = 1;
        for (int k = 0; k < n; ++k) {
            long long v = p[k];
            if (v < 0 || v >= N) { ok = 0; break; }
        }
        g_idx_is64 = ok;
    }
}

__global__ void hist_dst(const void* ei, int E, int N) {
    int i = blockIdx.x * blockDim.x + threadIdx.x;
    if (i >= E) return;
    int d = load_idx(ei, E + i);
    if ((unsigned)d < (unsigned)N) atomicAdd(&g_deg[d], 1);
}

__global__ void scan_block_sum(int N) {
    __shared__ int sh[256];
    int base = blockIdx.x * SCAN_TILE;
    int s = 0;
#pragma unroll
    for (int it = 0; it < 8; ++it) {
        int i = base + it * 256 + threadIdx.x;
        if (i < N) s += g_deg[i];
    }
    sh[threadIdx.x] = s;
    __syncthreads();
    for (int off = 128; off > 0; off >>= 1) {
        if (threadIdx.x < off) sh[threadIdx.x] += sh[threadIdx.x + off];
        __syncthreads();
    }
    if (threadIdx.x == 0) g_bsum[blockIdx.x] = sh[0];
}

__global__ void scan_bsums(int nb, int N) {
    __shared__ int sh[MAX_SCAN_BLOCKS];
    int v = (threadIdx.x < nb) ? g_bsum[threadIdx.x] : 0;
    sh[threadIdx.x] = v;
    __syncthreads();
    for (int off = 1; off < MAX_SCAN_BLOCKS; off <<= 1) {
        int t = (threadIdx.x >= off) ? sh[threadIdx.x - off] : 0;
        __syncthreads();
        sh[threadIdx.x] += t;
        __syncthreads();
    }
    if (threadIdx.x < nb) g_bpre[threadIdx.x] = sh[threadIdx.x] - v;
    if (threadIdx.x == nb - 1) g_row_ptr[N] = sh[threadIdx.x];
}

__global__ void scan_write(int N) {
    __shared__ int sh[256];
    int base = blockIdx.x * SCAN_TILE;
    int tstart = base + threadIdx.x * 8;
    int local[8];
    int s = 0;
#pragma unroll
    for (int j = 0; j < 8; ++j) {
        int i = tstart + j;
        int d = (i < N) ? g_deg[i] : 0;
        local[j] = s;
        s += d;
    }
    sh[threadIdx.x] = s;
    __syncthreads();
    for (int off = 1; off < 256; off <<= 1) {
        int t = (threadIdx.x >= off) ? sh[threadIdx.x - off] : 0;
        __syncthreads();
        sh[threadIdx.x] += t;
        __syncthreads();
    }
    int tpre = sh[threadIdx.x] - s + g_bpre[blockIdx.x];
#pragma unroll
    for (int j = 0; j < 8; ++j) {
        int i = tstart + j;
        if (i < N) {
            int r = tpre + local[j];
            g_row_ptr[i] = r;
            g_cursor[i] = r;
        }
    }
}

__global__ void fill_csr(const void* ei, int E, int N) {
    int i = blockIdx.x * blockDim.x + threadIdx.x;
    if (i >= E) return;
    int s = load_idx(ei, i);
    int d = load_idx(ei, E + i);
    if ((unsigned)s >= (unsigned)N || (unsigned)d >= (unsigned)N) return;
    int pos = atomicAdd(&g_cursor[d], 1);
    g_esrc[pos] = s;
}

// ---------------------------------------------------------------------------
// Plain aggregation (layer 0): z[node] = x[node] + sum x[src]
// ---------------------------------------------------------------------------
__global__ void aggregate(const float4* __restrict__ x, float4* __restrict__ znew, int N) {
    int node = (blockIdx.x * blockDim.x + threadIdx.x) >> 5;
    int lane = threadIdx.x & 31;
    if (node >= N) return;
    float4 acc = x[(size_t)node * 32 + lane];
    int e = g_row_ptr[node], end = g_row_ptr[node + 1];
    for (; e + 3 < end; e += 4) {
        int s0 = __ldg(&g_esrc[e]);
        int s1 = __ldg(&g_esrc[e + 1]);
        int s2 = __ldg(&g_esrc[e + 2]);
        int s3 = __ldg(&g_esrc[e + 3]);
        float4 v0 = x[(size_t)s0 * 32 + lane];
        float4 v1 = x[(size_t)s1 * 32 + lane];
        float4 v2 = x[(size_t)s2 * 32 + lane];
        float4 v3 = x[(size_t)s3 * 32 + lane];
        acc.x += v0.x + v1.x + v2.x + v3.x;
        acc.y += v0.y + v1.y + v2.y + v3.y;
        acc.z += v0.z + v1.z + v2.z + v3.z;
        acc.w += v0.w + v1.w + v2.w + v3.w;
    }
    for (; e < end; ++e) {
        int s = __ldg(&g_esrc[e]);
        float4 v = x[(size_t)s * 32 + lane];
        acc.x += v.x; acc.y += v.y; acc.z += v.z; acc.w += v.w;
    }
    znew[(size_t)node * 32 + lane] = acc;
}

// ---------------------------------------------------------------------------
// Fused BN+ReLU + aggregation (layers > 0): reads pre-BN z2 of prev layer,
// x = relu(a*v + b) applied inline; writes out[l-1] and the new agg buffer.
// ---------------------------------------------------------------------------
__global__ void aggregate_bn(const float4* __restrict__ zprev,
                             float4* __restrict__ outPrev,
                             float4* __restrict__ znew, int N) {
    int node = (blockIdx.x * blockDim.x + threadIdx.x) >> 5;
    int lane = threadIdx.x & 31;
    if (node >= N) return;
    float4 a = reinterpret_cast<const float4*>(g_scale)[lane];
    float4 b = reinterpret_cast<const float4*>(g_shift)[lane];

    float4 v = zprev[(size_t)node * 32 + lane];
    float4 own;
    own.x = fmaxf(fmaf(v.x, a.x, b.x), 0.f);
    own.y = fmaxf(fmaf(v.y, a.y, b.y), 0.f);
    own.z = fmaxf(fmaf(v.z, a.z, b.z), 0.f);
    own.w = fmaxf(fmaf(v.w, a.w, b.w), 0.f);
    outPrev[(size_t)node * 32 + lane] = own;

    float4 acc = own;
    int e = g_row_ptr[node], end = g_row_ptr[node + 1];
    for (; e + 1 < end; e += 2) {
        int s0 = __ldg(&g_esrc[e]);
        int s1 = __ldg(&g_esrc[e + 1]);
        float4 v0 = zprev[(size_t)s0 * 32 + lane];
        float4 v1 = zprev[(size_t)s1 * 32 + lane];
        acc.x += fmaxf(fmaf(v0.x, a.x, b.x), 0.f) + fmaxf(fmaf(v1.x, a.x, b.x), 0.f);
        acc.y += fmaxf(fmaf(v0.y, a.y, b.y), 0.f) + fmaxf(fmaf(v1.y, a.y, b.y), 0.f);
        acc.z += fmaxf(fmaf(v0.z, a.z, b.z), 0.f) + fmaxf(fmaf(v1.z, a.z, b.z), 0.f);
        acc.w += fmaxf(fmaf(v0.w, a.w, b.w), 0.f) + fmaxf(fmaf(v1.w, a.w, b.w), 0.f);
    }
    for (; e < end; ++e) {
        int s = __ldg(&g_esrc[e]);
        float4 vv = zprev[(size_t)s * 32 + lane];
        acc.x += fmaxf(fmaf(vv.x, a.x, b.x), 0.f);
        acc.y += fmaxf(fmaf(vv.y, a.y, b.y), 0.f);
        acc.z += fmaxf(fmaf(vv.z, a.z, b.z), 0.f);
        acc.w += fmaxf(fmaf(vv.w, a.w, b.w), 0.f);
    }
    znew[(size_t)node * 32 + lane] = acc;
}

// ---------------------------------------------------------------------------
// tf32 split + all-weights pre-split (and initial stats zero)
// ---------------------------------------------------------------------------
__device__ __forceinline__ void split_tf32(float x, uint32_t& hi, uint32_t& lo) {
    uint32_t h;
    asm("cvt.rna.tf32.f32 %0, %1;" : "=r"(h) : "f"(x));
    float r = x - __uint_as_float(h);
    uint32_t l;
    asm("cvt.rna.tf32.f32 %0, %1;" : "=r"(l) : "f"(r));
    hi = h; lo = l;
}

__global__ void split_all_w(const float* __restrict__ W1,
                            const float* __restrict__ W2, int L) {
    int i = blockIdx.x * blockDim.x + threadIdx.x;
    if (blockIdx.x == 0 && threadIdx.x < 2 * D) g_stats[threadIdx.x] = 0.f;
    int total = L * D * D;
    if (i < total) {           // W1 matrices
        int l = i / (D * D), r = i % (D * D);
        uint32_t h, lo;
        split_tf32(W1[i], h, lo);
        int o = (0 * MAXL + l) * D * D + r;
        g_WH[o] = h; g_WL[o] = lo;
    } else if (i < 2 * total) {  // W2 matrices
        int j = i - total;
        int l = j / (D * D), r = j % (D * D);
        uint32_t h, lo;
        split_tf32(W2[j], h, lo);
        int o = (1 * MAXL + l) * D * D + r;
        g_WH[o] = h; g_WL[o] = lo;
    }
}

__device__ __forceinline__ void mma_tf32(float c[4], const uint32_t a[4], const uint32_t b[2]) {
    asm volatile(
        "mma.sync.aligned.m16n8k8.row.col.f32.tf32.tf32.f32 "
        "{%0,%1,%2,%3}, {%4,%5,%6,%7}, {%8,%9}, {%0,%1,%2,%3};"
        : "+f"(c[0]), "+f"(c[1]), "+f"(c[2]), "+f"(c[3])
        : "r"(a[0]), "r"(a[1]), "r"(a[2]), "r"(a[3]), "r"(b[0]), "r"(b[1]));
}

// ---------------------------------------------------------------------------
// Tensor-core GEMM, 3xTF32, runtime A/C pointers, weight offset into g_WH/WL.
// RELU=1: relu epilogue. STATS=1: fused BN column stats.
// ---------------------------------------------------------------------------
template <int RELU, int STATS>
__global__ __launch_bounds__(256) void gemm_tc(
    const float* __restrict__ A, float* __restrict__ C,
    int woff, const float* __restrict__ bias, int N) {

    __shared__ uint32_t AsH[128][20], AsL[128][20];
    __shared__ uint32_t BsH[16][136], BsL[16][136];

    int tid = threadIdx.x;
    int warp = tid >> 5, lane = tid & 31;
    int wr = warp >> 1;
    int wc = warp & 1;
    int rowBase = blockIdx.x * 128;
    int lq = lane & 3;
    int lg = lane >> 2;

    float acc[2][8][4] = {};

    for (int k0 = 0; k0 < D; k0 += 16) {
#pragma unroll
        for (int it = 0; it < 2; ++it) {
            int i = tid + it * 256;
            int row = rowBase + (i >> 2);
            int gr = row < N ? row : N - 1;
            float4 v = *reinterpret_cast<const float4*>(A + (size_t)gr * D + k0 + (i & 3) * 4);
            int r = i >> 2, c = (i & 3) * 4;
            uint32_t h, l;
            split_tf32(v.x, h, l); AsH[r][c + 0] = h; AsL[r][c + 0] = l;
            split_tf32(v.y, h, l); AsH[r][c + 1] = h; AsL[r][c + 1] = l;
            split_tf32(v.z, h, l); AsH[r][c + 2] = h; AsL[r][c + 2] = l;
            split_tf32(v.w, h, l); AsH[r][c + 3] = h; AsL[r][c + 3] = l;
        }
#pragma unroll
        for (int it = 0; it < 2; ++it) {
            int i = tid + it * 256;
            int row = i >> 5, c4 = (i & 31) * 4;
            *reinterpret_cast<uint4*>(&BsH[row][c4]) =
                *reinterpret_cast<const uint4*>(&g_WH[woff + (size_t)(k0 + row) * D + c4]);
            *reinterpret_cast<uint4*>(&BsL[row][c4]) =
                *reinterpret_cast<const uint4*>(&g_WL[woff + (size_t)(k0 + row) * D + c4]);
        }
        __syncthreads();

#pragma unroll
        for (int ks = 0; ks < 2; ++ks) {
            int kb = ks * 8;
            uint32_t ah[2][4], al[2][4];
#pragma unroll
            for (int mt = 0; mt < 2; ++mt) {
                int r0 = wr * 32 + mt * 16 + lg;
                int kk = kb + lq;
                ah[mt][0] = AsH[r0][kk];         al[mt][0] = AsL[r0][kk];
                ah[mt][1] = AsH[r0 + 8][kk];     al[mt][1] = AsL[r0 + 8][kk];
                ah[mt][2] = AsH[r0][kk + 4];     al[mt][2] = AsL[r0][kk + 4];
                ah[mt][3] = AsH[r0 + 8][kk + 4]; al[mt][3] = AsL[r0 + 8][kk + 4];
            }
#pragma unroll
            for (int nt = 0; nt < 8; ++nt) {
                int n0 = wc * 64 + nt * 8 + lg;
                int kk = kb + lq;
                uint32_t bh[2], bl[2];
                bh[0] = BsH[kk][n0];     bl[0] = BsL[kk][n0];
                bh[1] = BsH[kk + 4][n0]; bl[1] = BsL[kk + 4][n0];
#pragma unroll
                for (int mt = 0; mt < 2; ++mt) {
                    mma_tf32(acc[mt][nt], ah[mt], bh);
                    mma_tf32(acc[mt][nt], al[mt], bh);
                    mma_tf32(acc[mt][nt], ah[mt], bl);
                }
            }
        }
        __syncthreads();
    }

#pragma unroll
    for (int nt = 0; nt < 8; ++nt) {
        int col = wc * 64 + nt * 8 + 2 * lq;
        float b0 = bias[col], b1 = bias[col + 1];
        float s0 = 0.f, s1 = 0.f, q0 = 0.f, q1 = 0.f;
#pragma unroll
        for (int mt = 0; mt < 2; ++mt) {
            int r0 = rowBase + wr * 32 + mt * 16 + lg;
            int r1 = r0 + 8;
            float v00 = acc[mt][nt][0] + b0;
            float v01 = acc[mt][nt][1] + b1;
            float v10 = acc[mt][nt][2] + b0;
            float v11 = acc[mt][nt][3] + b1;
            if (RELU) {
                v00 = fmaxf(v00, 0.f); v01 = fmaxf(v01, 0.f);
                v10 = fmaxf(v10, 0.f); v11 = fmaxf(v11, 0.f);
            }
            if (r0 < N) {
                *reinterpret_cast<float2*>(C + (size_t)r0 * D + col) = make_float2(v00, v01);
                if (STATS) { s0 += v00; s1 += v01; q0 += v00 * v00; q1 += v01 * v01; }
            }
            if (r1 < N) {
                *reinterpret_cast<float2*>(C + (size_t)r1 * D + col) = make_float2(v10, v11);
                if (STATS) { s0 += v10; s1 += v11; q0 += v10 * v10; q1 += v11 * v11; }
            }
        }
        if (STATS) {
#pragma unroll
            for (int m = 4; m <= 16; m <<= 1) {
                s0 += __shfl_xor_sync(0xffffffffu, s0, m);
                s1 += __shfl_xor_sync(0xffffffffu, s1, m);
                q0 += __shfl_xor_sync(0xffffffffu, q0, m);
                q1 += __shfl_xor_sync(0xffffffffu, q1, m);
            }
            if (lg == 0) {
                atomicAdd(&g_stats[col], s0);
                atomicAdd(&g_stats[col + 1], s1);
                atomicAdd(&g_stats[D + col], q0);
                atomicAdd(&g_stats[D + col + 1], q1);
            }
        }
    }
}

// ---------------------------------------------------------------------------
// BN finalize: compute scale/shift then re-zero stats for the next layer.
// ---------------------------------------------------------------------------
__global__ void bn_finalize(const float* __restrict__ gamma,
                            const float* __restrict__ beta, float invN) {
    int c = threadIdx.x;
    float s = g_stats[c], q = g_stats[D + c];
    float mean = s * invN;
    float var = fmaxf(q * invN - mean * mean, 0.f);
    float a = gamma[c] * rsqrtf(var + 1e-5f);
    g_scale[c] = a;
    g_shift[c] = beta[c] - mean * a;
    g_stats[c] = 0.f;
    g_stats[D + c] = 0.f;
}

__global__ void bn_relu(const float4* __restrict__ z2, float4* __restrict__ y, int n4) {
    int i = blockIdx.x * blockDim.x + threadIdx.x;
    if (i >= n4) return;
    int c = i & (D / 4 - 1);
    float4 a = *reinterpret_cast<const float4*>(&g_scale[c * 4]);
    float4 b = *reinterpret_cast<const float4*>(&g_shift[c * 4]);
    float4 v = z2[i];
    v.x = fmaxf(fmaf(v.x, a.x, b.x), 0.f);
    v.y = fmaxf(fmaf(v.y, a.y, b.y), 0.f);
    v.z = fmaxf(fmaf(v.z, a.z, b.z), 0.f);
    v.w = fmaxf(fmaf(v.w, a.w, b.w), 0.f);
    y[i] = v;
}

// ---------------------------------------------------------------------------
extern "C" void kernel_launch(void* const* d_in, const int* in_sizes, int n_in,
                              void* d_out, int out_size) {
    const float* h     = (const float*)d_in[0];
    const void*  ei    = d_in[1];
    const float* W1    = (const float*)d_in[2];
    const float* b1    = (const float*)d_in[3];
    const float* W2    = (const float*)d_in[4];
    const float* b2    = (const float*)d_in[5];
    const float* gamma = (const float*)d_in[6];
    const float* beta  = (const float*)d_in[7];
    float*       out   = (float*)d_out;

    int N = in_sizes[0] / D;
    int E = in_sizes[1] / 2;
    int L = in_sizes[2] / (D * D);

    int n4 = N * (D / 4);
    int vecBlocks = (n4 + 255) / 256;
    int eBlocks = (E + 255) / 256;
    int nBlocks = (N + 255) / 256;
    int aggBlocks = (N * 32 + 255) / 256;
    int gemmBlocks = (N + 127) / 128;
    int scanBlocks = (N + SCAN_TILE - 1) / SCAN_TILE;

    // Ping-pong scratch pointers (device symbols -> raw pointers; host API, no alloc)
    void *pz = nullptr, *ph = nullptr;
    cudaGetSymbolAddress(&pz, g_z);
    cudaGetSymbolAddress(&ph, g_h);
    float* A = (float*)pz;
    float* B = (float*)ph;

    // CSR build (once; edge list is layer-invariant)
    zero_deg_probe<<<nBlocks, 256>>>(ei, E, N);
    hist_dst<<<eBlocks, 256>>>(ei, E, N);
    scan_block_sum<<<scanBlocks, 256>>>(N);
    scan_bsums<<<1, MAX_SCAN_BLOCKS>>>(scanBlocks, N);
    scan_write<<<scanBlocks, 256>>>(N);
    fill_csr<<<eBlocks, 256>>>(ei, E, N);
    // Pre-split all weights + zero stats
    split_all_w<<<(2 * L * D * D + 255) / 256, 256>>>(W1, W2, L);

    for (int l = 0; l < L; ++l) {
        int w1off = (0 * MAXL + l) * D * D;
        int w2off = (1 * MAXL + l) * D * D;
        if (l == 0) {
            aggregate<<<aggBlocks, 256>>>((const float4*)h, (float4*)A, N);
            gemm_tc<1, 0><<<gemmBlocks, 256>>>(A, B, w1off, b1 + l * D, N);
            gemm_tc<0, 1><<<gemmBlocks, 256>>>(B, A, w2off, b2 + l * D, N);
            bn_finalize<<<1, D>>>(gamma + l * D, beta + l * D, 1.0f / (float)N);
            // z2 lives in A
        } else {
            float* yPrev = out + (size_t)(l - 1) * N * D;
            aggregate_bn<<<aggBlocks, 256>>>((const float4*)A, (float4*)yPrev, (float4*)B, N);
            gemm_tc<1, 0><<<gemmBlocks, 256>>>(B, A, w1off, b1 + l * D, N);
            gemm_tc<0, 1><<<gemmBlocks, 256>>>(A, B, w2off, b2 + l * D, N);
            bn_finalize<<<1, D>>>(gamma + l * D, beta + l * D, 1.0f / (float)N);
            // z2 lives in B -> swap so next layer reads from A
            float* t = A; A = B; B = t;
        }
    }
    bn_relu<<<vecBlocks, 256>>>((const float4*)A, (float4*)(out + (size_t)(L - 1) * N * D), n4);
}

// round 9
// speedup vs baseline: 1.6295x; 1.0839x over previous
#include <cuda_runtime.h>
#include <cstdint>

#define D 128
#define MAXN 50000
#define MAXE 800000
#define MAXL 8
#define SCAN_TILE 2048
#define MAX_SCAN_BLOCKS 256

// Dynamic smem layout for mlp_fused (bytes)
#define SH_ROW 132
#define OFF_SH   0
#define OFF_ASH  (128 * SH_ROW * 4)                 // 67584
#define OFF_ASL  (OFF_ASH + 128 * 20 * 4)           // 77824
#define OFF_BSH  (OFF_ASL + 128 * 20 * 4)           // 88064
#define OFF_BSL  (OFF_BSH + 16 * 136 * 4)           // 96768
#define SMEM_TOTAL_FUSED (OFF_BSL + 16 * 136 * 4)   // 105472

// Scratch (no allocations allowed in kernel_launch).
__device__ __align__(16) float g_z[(size_t)MAXN * D];
__device__ __align__(16) float g_h[(size_t)MAXN * D];
__device__ __align__(16) float g_stats[2 * D];
__device__ __align__(16) float g_scale[D];
__device__ __align__(16) float g_shift[D];
__device__ __align__(16) uint32_t g_WH[2 * MAXL * D * D];
__device__ __align__(16) uint32_t g_WL[2 * MAXL * D * D];
__device__ int g_idx_is64;
__device__ int g_deg[MAXN];
__device__ int g_row_ptr[MAXN + 1];
__device__ int g_cursor[MAXN];
__device__ int g_esrc[MAXE];
__device__ int g_bsum[MAX_SCAN_BLOCKS];
__device__ int g_bpre[MAX_SCAN_BLOCKS];

// ---------------------------------------------------------------------------
__device__ __forceinline__ int load_idx(const void* ei, int i) {
    if (g_idx_is64) return (int)__ldg(&((const long long*)ei)[i]);
    return __ldg(&((const int*)ei)[i]);
}

__global__ void zero_deg_probe(const void* ei, int E, int N) {
    int i = blockIdx.x * blockDim.x + threadIdx.x;
    if (i < N) g_deg[i] = 0;
    if (blockIdx.x == 0 && threadIdx.x == 0) {
        const long long* p = (const long long*)ei;
        int n = E < 64 ? E : 64;
        int ok = 1;
        for (int k = 0; k < n; ++k) {
            long long v = p[k];
            if (v < 0 || v >= N) { ok = 0; break; }
        }
        g_idx_is64 = ok;
    }
}

__global__ void hist_dst(const void* ei, int E, int N) {
    int i = blockIdx.x * blockDim.x + threadIdx.x;
    if (i >= E) return;
    int d = load_idx(ei, E + i);
    if ((unsigned)d < (unsigned)N) atomicAdd(&g_deg[d], 1);
}

__global__ void scan_block_sum(int N) {
    __shared__ int sh[256];
    int base = blockIdx.x * SCAN_TILE;
    int s = 0;
#pragma unroll
    for (int it = 0; it < 8; ++it) {
        int i = base + it * 256 + threadIdx.x;
        if (i < N) s += g_deg[i];
    }
    sh[threadIdx.x] = s;
    __syncthreads();
    for (int off = 128; off > 0; off >>= 1) {
        if (threadIdx.x < off) sh[threadIdx.x] += sh[threadIdx.x + off];
        __syncthreads();
    }
    if (threadIdx.x == 0) g_bsum[blockIdx.x] = sh[0];
}

__global__ void scan_bsums(int nb, int N) {
    __shared__ int sh[MAX_SCAN_BLOCKS];
    int v = (threadIdx.x < nb) ? g_bsum[threadIdx.x] : 0;
    sh[threadIdx.x] = v;
    __syncthreads();
    for (int off = 1; off < MAX_SCAN_BLOCKS; off <<= 1) {
        int t = (threadIdx.x >= off) ? sh[threadIdx.x - off] : 0;
        __syncthreads();
        sh[threadIdx.x] += t;
        __syncthreads();
    }
    if (threadIdx.x < nb) g_bpre[threadIdx.x] = sh[threadIdx.x] - v;
    if (threadIdx.x == nb - 1) g_row_ptr[N] = sh[threadIdx.x];
}

__global__ void scan_write(int N) {
    __shared__ int sh[256];
    int base = blockIdx.x * SCAN_TILE;
    int tstart = base + threadIdx.x * 8;
    int local[8];
    int s = 0;
#pragma unroll
    for (int j = 0; j < 8; ++j) {
        int i = tstart + j;
        int d = (i < N) ? g_deg[i] : 0;
        local[j] = s;
        s += d;
    }
    sh[threadIdx.x] = s;
    __syncthreads();
    for (int off = 1; off < 256; off <<= 1) {
        int t = (threadIdx.x >= off) ? sh[threadIdx.x - off] : 0;
        __syncthreads();
        sh[threadIdx.x] += t;
        __syncthreads();
    }
    int tpre = sh[threadIdx.x] - s + g_bpre[blockIdx.x];
#pragma unroll
    for (int j = 0; j < 8; ++j) {
        int i = tstart + j;
        if (i < N) {
            int r = tpre + local[j];
            g_row_ptr[i] = r;
            g_cursor[i] = r;
        }
    }
}

__global__ void fill_csr(const void* ei, int E, int N) {
    int i = blockIdx.x * blockDim.x + threadIdx.x;
    if (i >= E) return;
    int s = load_idx(ei, i);
    int d = load_idx(ei, E + i);
    if ((unsigned)s >= (unsigned)N || (unsigned)d >= (unsigned)N) return;
    int pos = atomicAdd(&g_cursor[d], 1);
    g_esrc[pos] = s;
}

// ---------------------------------------------------------------------------
__global__ void aggregate(const float4* __restrict__ x, float4* __restrict__ znew, int N) {
    int node = (blockIdx.x * blockDim.x + threadIdx.x) >> 5;
    int lane = threadIdx.x & 31;
    if (node >= N) return;
    float4 acc = x[(size_t)node * 32 + lane];
    int e = g_row_ptr[node], end = g_row_ptr[node + 1];
    for (; e + 3 < end; e += 4) {
        int s0 = __ldg(&g_esrc[e]);
        int s1 = __ldg(&g_esrc[e + 1]);
        int s2 = __ldg(&g_esrc[e + 2]);
        int s3 = __ldg(&g_esrc[e + 3]);
        float4 v0 = x[(size_t)s0 * 32 + lane];
        float4 v1 = x[(size_t)s1 * 32 + lane];
        float4 v2 = x[(size_t)s2 * 32 + lane];
        float4 v3 = x[(size_t)s3 * 32 + lane];
        acc.x += v0.x + v1.x + v2.x + v3.x;
        acc.y += v0.y + v1.y + v2.y + v3.y;
        acc.z += v0.z + v1.z + v2.z + v3.z;
        acc.w += v0.w + v1.w + v2.w + v3.w;
    }
    for (; e < end; ++e) {
        int s = __ldg(&g_esrc[e]);
        float4 v = x[(size_t)s * 32 + lane];
        acc.x += v.x; acc.y += v.y; acc.z += v.z; acc.w += v.w;
    }
    znew[(size_t)node * 32 + lane] = acc;
}

__global__ void aggregate_bn(const float4* __restrict__ zprev,
                             float4* __restrict__ outPrev,
                             float4* __restrict__ znew, int N) {
    int node = (blockIdx.x * blockDim.x + threadIdx.x) >> 5;
    int lane = threadIdx.x & 31;
    if (node >= N) return;
    float4 a = reinterpret_cast<const float4*>(g_scale)[lane];
    float4 b = reinterpret_cast<const float4*>(g_shift)[lane];

    float4 v = zprev[(size_t)node * 32 + lane];
    float4 own;
    own.x = fmaxf(fmaf(v.x, a.x, b.x), 0.f);
    own.y = fmaxf(fmaf(v.y, a.y, b.y), 0.f);
    own.z = fmaxf(fmaf(v.z, a.z, b.z), 0.f);
    own.w = fmaxf(fmaf(v.w, a.w, b.w), 0.f);
    outPrev[(size_t)node * 32 + lane] = own;

    float4 acc = own;
    int e = g_row_ptr[node], end = g_row_ptr[node + 1];
    for (; e + 1 < end; e += 2) {
        int s0 = __ldg(&g_esrc[e]);
        int s1 = __ldg(&g_esrc[e + 1]);
        float4 v0 = zprev[(size_t)s0 * 32 + lane];
        float4 v1 = zprev[(size_t)s1 * 32 + lane];
        acc.x += fmaxf(fmaf(v0.x, a.x, b.x), 0.f) + fmaxf(fmaf(v1.x, a.x, b.x), 0.f);
        acc.y += fmaxf(fmaf(v0.y, a.y, b.y), 0.f) + fmaxf(fmaf(v1.y, a.y, b.y), 0.f);
        acc.z += fmaxf(fmaf(v0.z, a.z, b.z), 0.f) + fmaxf(fmaf(v1.z, a.z, b.z), 0.f);
        acc.w += fmaxf(fmaf(v0.w, a.w, b.w), 0.f) + fmaxf(fmaf(v1.w, a.w, b.w), 0.f);
    }
    for (; e < end; ++e) {
        int s = __ldg(&g_esrc[e]);
        float4 vv = zprev[(size_t)s * 32 + lane];
        acc.x += fmaxf(fmaf(vv.x, a.x, b.x), 0.f);
        acc.y += fmaxf(fmaf(vv.y, a.y, b.y), 0.f);
        acc.z += fmaxf(fmaf(vv.z, a.z, b.z), 0.f);
        acc.w += fmaxf(fmaf(vv.w, a.w, b.w), 0.f);
    }
    znew[(size_t)node * 32 + lane] = acc;
}

// ---------------------------------------------------------------------------
__device__ __forceinline__ void split_tf32(float x, uint32_t& hi, uint32_t& lo) {
    uint32_t h;
    asm("cvt.rna.tf32.f32 %0, %1;" : "=r"(h) : "f"(x));
    float r = x - __uint_as_float(h);
    uint32_t l;
    asm("cvt.rna.tf32.f32 %0, %1;" : "=r"(l) : "f"(r));
    hi = h; lo = l;
}

__global__ void split_all_w(const float* __restrict__ W1,
                            const float* __restrict__ W2, int L) {
    int i = blockIdx.x * blockDim.x + threadIdx.x;
    if (blockIdx.x == 0 && threadIdx.x < 2 * D) g_stats[threadIdx.x] = 0.f;
    int total = L * D * D;
    if (i < total) {
        int l = i / (D * D), r = i % (D * D);
        uint32_t h, lo;
        split_tf32(W1[i], h, lo);
        int o = (0 * MAXL + l) * D * D + r;
        g_WH[o] = h; g_WL[o] = lo;
    } else if (i < 2 * total) {
        int j = i - total;
        int l = j / (D * D), r = j % (D * D);
        uint32_t h, lo;
        split_tf32(W2[j], h, lo);
        int o = (1 * MAXL + l) * D * D + r;
        g_WH[o] = h; g_WL[o] = lo;
    }
}

__device__ __forceinline__ void mma_tf32(float c[4], const uint32_t a[4], const uint32_t b[2]) {
    asm volatile(
        "mma.sync.aligned.m16n8k8.row.col.f32.tf32.tf32.f32 "
        "{%0,%1,%2,%3}, {%4,%5,%6,%7}, {%8,%9}, {%0,%1,%2,%3};"
        : "+f"(c[0]), "+f"(c[1]), "+f"(c[2]), "+f"(c[3])
        : "r"(a[0]), "r"(a[1]), "r"(a[2]), "r"(a[3]), "r"(b[0]), "r"(b[1]));
}

// ---------------------------------------------------------------------------
// Fused 2-layer MLP: z2 = relu(z@W1+b1)@W2+b2, one block = 128 rows.
// Phase 1 accumulates H, parks it (bias+relu) in fp32 smem, phase 2 consumes it.
// Epilogue 2 writes z2 and fused BN column stats. 3xTF32 throughout.
// ---------------------------------------------------------------------------
__device__ __forceinline__ void mma_block_step(
    const uint32_t* AsH, const uint32_t* AsL,
    const uint32_t* BsH, const uint32_t* BsL,
    float acc[2][8][4], int wr, int wc, int lq, int lg) {
#pragma unroll
    for (int ks = 0; ks < 2; ++ks) {
        int kb = ks * 8;
        uint32_t ah[2][4], al[2][4];
#pragma unroll
        for (int mt = 0; mt < 2; ++mt) {
            int r0 = wr * 32 + mt * 16 + lg;
            int kk = kb + lq;
            ah[mt][0] = AsH[r0 * 20 + kk];           al[mt][0] = AsL[r0 * 20 + kk];
            ah[mt][1] = AsH[(r0 + 8) * 20 + kk];     al[mt][1] = AsL[(r0 + 8) * 20 + kk];
            ah[mt][2] = AsH[r0 * 20 + kk + 4];       al[mt][2] = AsL[r0 * 20 + kk + 4];
            ah[mt][3] = AsH[(r0 + 8) * 20 + kk + 4]; al[mt][3] = AsL[(r0 + 8) * 20 + kk + 4];
        }
#pragma unroll
        for (int nt = 0; nt < 8; ++nt) {
            int n0 = wc * 64 + nt * 8 + lg;
            int kk = kb + lq;
            uint32_t bh[2], bl[2];
            bh[0] = BsH[kk * 136 + n0];       bl[0] = BsL[kk * 136 + n0];
            bh[1] = BsH[(kk + 4) * 136 + n0]; bl[1] = BsL[(kk + 4) * 136 + n0];
#pragma unroll
            for (int mt = 0; mt < 2; ++mt) {
                mma_tf32(acc[mt][nt], ah[mt], bh);
                mma_tf32(acc[mt][nt], al[mt], bh);
                mma_tf32(acc[mt][nt], ah[mt], bl);
            }
        }
    }
}

__global__ __launch_bounds__(256, 2) void mlp_fused(
    const float* __restrict__ A, float* __restrict__ C,
    int w1off, int w2off,
    const float* __restrict__ b1, const float* __restrict__ b2, int N) {

    extern __shared__ char smem[];
    float*    sH  = (float*)(smem + OFF_SH);      // [128][SH_ROW]
    uint32_t* AsH = (uint32_t*)(smem + OFF_ASH);  // [128][20]
    uint32_t* AsL = (uint32_t*)(smem + OFF_ASL);
    uint32_t* BsH = (uint32_t*)(smem + OFF_BSH);  // [16][136]
    uint32_t* BsL = (uint32_t*)(smem + OFF_BSL);

    int tid = threadIdx.x;
    int warp = tid >> 5, lane = tid & 31;
    int wr = warp >> 1;
    int wc = warp & 1;
    int rowBase = blockIdx.x * 128;
    int lq = lane & 3;
    int lg = lane >> 2;

    float acc[2][8][4] = {};

    // ---------------- Phase 1: H = z @ W1 ----------------
    for (int k0 = 0; k0 < D; k0 += 16) {
#pragma unroll
        for (int it = 0; it < 2; ++it) {
            int i = tid + it * 256;
            int row = rowBase + (i >> 2);
            int gr = row < N ? row : N - 1;
            float4 v = *reinterpret_cast<const float4*>(A + (size_t)gr * D + k0 + (i & 3) * 4);
            int r = i >> 2, c = (i & 3) * 4;
            uint32_t h, l;
            split_tf32(v.x, h, l); AsH[r * 20 + c + 0] = h; AsL[r * 20 + c + 0] = l;
            split_tf32(v.y, h, l); AsH[r * 20 + c + 1] = h; AsL[r * 20 + c + 1] = l;
            split_tf32(v.z, h, l); AsH[r * 20 + c + 2] = h; AsL[r * 20 + c + 2] = l;
            split_tf32(v.w, h, l); AsH[r * 20 + c + 3] = h; AsL[r * 20 + c + 3] = l;
        }
#pragma unroll
        for (int it = 0; it < 2; ++it) {
            int i = tid + it * 256;
            int row = i >> 5, c4 = (i & 31) * 4;
            *reinterpret_cast<uint4*>(&BsH[row * 136 + c4]) =
                *reinterpret_cast<const uint4*>(&g_WH[w1off + (size_t)(k0 + row) * D + c4]);
            *reinterpret_cast<uint4*>(&BsL[row * 136 + c4]) =
                *reinterpret_cast<const uint4*>(&g_WL[w1off + (size_t)(k0 + row) * D + c4]);
        }
        __syncthreads();
        mma_block_step(AsH, AsL, BsH, BsL, acc, wr, wc, lq, lg);
        __syncthreads();
    }

    // Epilogue 1: bias + relu -> sH (covers each element exactly once)
#pragma unroll
    for (int nt = 0; nt < 8; ++nt) {
        int col = wc * 64 + nt * 8 + 2 * lq;
        float b0 = b1[col], bcol1 = b1[col + 1];
#pragma unroll
        for (int mt = 0; mt < 2; ++mt) {
            int r0 = wr * 32 + mt * 16 + lg;
            int r1 = r0 + 8;
            sH[r0 * SH_ROW + col]     = fmaxf(acc[mt][nt][0] + b0, 0.f);
            sH[r0 * SH_ROW + col + 1] = fmaxf(acc[mt][nt][1] + bcol1, 0.f);
            sH[r1 * SH_ROW + col]     = fmaxf(acc[mt][nt][2] + b0, 0.f);
            sH[r1 * SH_ROW + col + 1] = fmaxf(acc[mt][nt][3] + bcol1, 0.f);
            acc[mt][nt][0] = 0.f; acc[mt][nt][1] = 0.f;
            acc[mt][nt][2] = 0.f; acc[mt][nt][3] = 0.f;
        }
    }
    __syncthreads();

    // ---------------- Phase 2: z2 = H @ W2 ----------------
    for (int k0 = 0; k0 < D; k0 += 16) {
#pragma unroll
        for (int it = 0; it < 2; ++it) {
            int i = tid + it * 256;
            int r = i >> 2, c = (i & 3) * 4;
            float4 v = *reinterpret_cast<const float4*>(&sH[r * SH_ROW + k0 + c]);
            uint32_t h, l;
            split_tf32(v.x, h, l); AsH[r * 20 + c + 0] = h; AsL[r * 20 + c + 0] = l;
            split_tf32(v.y, h, l); AsH[r * 20 + c + 1] = h; AsL[r * 20 + c + 1] = l;
            split_tf32(v.z, h, l); AsH[r * 20 + c + 2] = h; AsL[r * 20 + c + 2] = l;
            split_tf32(v.w, h, l); AsH[r * 20 + c + 3] = h; AsL[r * 20 + c + 3] = l;
        }
#pragma unroll
        for (int it = 0; it < 2; ++it) {
            int i = tid + it * 256;
            int row = i >> 5, c4 = (i & 31) * 4;
            *reinterpret_cast<uint4*>(&BsH[row * 136 + c4]) =
                *reinterpret_cast<const uint4*>(&g_WH[w2off + (size_t)(k0 + row) * D + c4]);
            *reinterpret_cast<uint4*>(&BsL[row * 136 + c4]) =
                *reinterpret_cast<const uint4*>(&g_WL[w2off + (size_t)(k0 + row) * D + c4]);
        }
        __syncthreads();
        mma_block_step(AsH, AsL, BsH, BsL, acc, wr, wc, lq, lg);
        __syncthreads();
    }

    // Epilogue 2: bias, store z2, fused BN stats
#pragma unroll
    for (int nt = 0; nt < 8; ++nt) {
        int col = wc * 64 + nt * 8 + 2 * lq;
        float b0 = b2[col], bcol1 = b2[col + 1];
        float s0 = 0.f, s1 = 0.f, q0 = 0.f, q1 = 0.f;
#pragma unroll
        for (int mt = 0; mt < 2; ++mt) {
            int r0 = rowBase + wr * 32 + mt * 16 + lg;
            int r1 = r0 + 8;
            float v00 = acc[mt][nt][0] + b0;
            float v01 = acc[mt][nt][1] + bcol1;
            float v10 = acc[mt][nt][2] + b0;
            float v11 = acc[mt][nt][3] + bcol1;
            if (r0 < N) {
                *reinterpret_cast<float2*>(C + (size_t)r0 * D + col) = make_float2(v00, v01);
                s0 += v00; s1 += v01; q0 += v00 * v00; q1 += v01 * v01;
            }
            if (r1 < N) {
                *reinterpret_cast<float2*>(C + (size_t)r1 * D + col) = make_float2(v10, v11);
                s0 += v10; s1 += v11; q0 += v10 * v10; q1 += v11 * v11;
            }
        }
#pragma unroll
        for (int m = 4; m <= 16; m <<= 1) {
            s0 += __shfl_xor_sync(0xffffffffu, s0, m);
            s1 += __shfl_xor_sync(0xffffffffu, s1, m);
            q0 += __shfl_xor_sync(0xffffffffu, q0, m);
            q1 += __shfl_xor_sync(0xffffffffu, q1, m);
        }
        if (lg == 0) {
            atomicAdd(&g_stats[col], s0);
            atomicAdd(&g_stats[col + 1], s1);
            atomicAdd(&g_stats[D + col], q0);
            atomicAdd(&g_stats[D + col + 1], q1);
        }
    }
}

// ---------------------------------------------------------------------------
__global__ void bn_finalize(const float* __restrict__ gamma,
                            const float* __restrict__ beta, float invN) {
    int c = threadIdx.x;
    float s = g_stats[c], q = g_stats[D + c];
    float mean = s * invN;
    float var = fmaxf(q * invN - mean * mean, 0.f);
    float a = gamma[c] * rsqrtf(var + 1e-5f);
    g_scale[c] = a;
    g_shift[c] = beta[c] - mean * a;
    g_stats[c] = 0.f;
    g_stats[D + c] = 0.f;
}

__global__ void bn_relu(const float4* __restrict__ z2, float4* __restrict__ y, int n4) {
    int i = blockIdx.x * blockDim.x + threadIdx.x;
    if (i >= n4) return;
    int c = i & (D / 4 - 1);
    float4 a = *reinterpret_cast<const float4*>(&g_scale[c * 4]);
    float4 b = *reinterpret_cast<const float4*>(&g_shift[c * 4]);
    float4 v = z2[i];
    v.x = fmaxf(fmaf(v.x, a.x, b.x), 0.f);
    v.y = fmaxf(fmaf(v.y, a.y, b.y), 0.f);
    v.z = fmaxf(fmaf(v.z, a.z, b.z), 0.f);
    v.w = fmaxf(fmaf(v.w, a.w, b.w), 0.f);
    y[i] = v;
}

// ---------------------------------------------------------------------------
extern "C" void kernel_launch(void* const* d_in, const int* in_sizes, int n_in,
                              void* d_out, int out_size) {
    const float* h     = (const float*)d_in[0];
    const void*  ei    = d_in[1];
    const float* W1    = (const float*)d_in[2];
    const float* b1    = (const float*)d_in[3];
    const float* W2    = (const float*)d_in[4];
    const float* b2    = (const float*)d_in[5];
    const float* gamma = (const float*)d_in[6];
    const float* beta  = (const float*)d_in[7];
    float*       out   = (float*)d_out;

    int N = in_sizes[0] / D;
    int E = in_sizes[1] / 2;
    int L = in_sizes[2] / (D * D);

    int n4 = N * (D / 4);
    int vecBlocks = (n4 + 255) / 256;
    int eBlocks = (E + 255) / 256;
    int nBlocks = (N + 255) / 256;
    int aggBlocks = (N * 32 + 255) / 256;
    int gemmBlocks = (N + 127) / 128;
    int scanBlocks = (N + SCAN_TILE - 1) / SCAN_TILE;

    static int smem_set = 0;
    if (!smem_set) {
        cudaFuncSetAttribute(mlp_fused, cudaFuncAttributeMaxDynamicSharedMemorySize,
                             SMEM_TOTAL_FUSED);
        smem_set = 1;
    }

    void *pz = nullptr, *ph = nullptr;
    cudaGetSymbolAddress(&pz, g_z);
    cudaGetSymbolAddress(&ph, g_h);
    float* A = (float*)pz;
    float* B = (float*)ph;

    zero_deg_probe<<<nBlocks, 256>>>(ei, E, N);
    hist_dst<<<eBlocks, 256>>>(ei, E, N);
    scan_block_sum<<<scanBlocks, 256>>>(N);
    scan_bsums<<<1, MAX_SCAN_BLOCKS>>>(scanBlocks, N);
    scan_write<<<scanBlocks, 256>>>(N);
    fill_csr<<<eBlocks, 256>>>(ei, E, N);
    split_all_w<<<(2 * L * D * D + 255) / 256, 256>>>(W1, W2, L);

    for (int l = 0; l < L; ++l) {
        int w1off = (0 * MAXL + l) * D * D;
        int w2off = (1 * MAXL + l) * D * D;
        if (l == 0) {
            aggregate<<<aggBlocks, 256>>>((const float4*)h, (float4*)A, N);
            mlp_fused<<<gemmBlocks, 256, SMEM_TOTAL_FUSED>>>(
                A, B, w1off, w2off, b1 + l * D, b2 + l * D, N);
            bn_finalize<<<1, D>>>(gamma + l * D, beta + l * D, 1.0f / (float)N);
            // z2 lives in B -> make A hold z2 for next layer
            float* t = A; A = B; B = t;
        } else {
            float* yPrev = out + (size_t)(l - 1) * N * D;
            aggregate_bn<<<aggBlocks, 256>>>((const float4*)A, (float4*)yPrev, (float4*)B, N);
            mlp_fused<<<gemmBlocks, 256, SMEM_TOTAL_FUSED>>>(
                B, A, w1off, w2off, b1 + l * D, b2 + l * D, N);
            bn_finalize<<<1, D>>>(gamma + l * D, beta + l * D, 1.0f / (float)N);
            // z2 lives in A (already the read buffer for next layer)
        }
    }
    bn_relu<<<vecBlocks, 256>>>((const float4*)A, (float4*)(out + (size_t)(L - 1) * N * D), n4);
}

// round 10
// speedup vs baseline: 1.6304x; 1.0005x over previous
#include <cuda_runtime.h>
#include <cstdint>

#define D 128
#define MAXN 50000
#define MAXE 800000
#define MAXL 8
#define SCAN_TILE 2048
#define MAX_SCAN_BLOCKS 256

// Dynamic smem layout for mlp_fused (bytes)
#define SH_ROW 132
#define OFF_SH   0
#define OFF_ASH  (128 * SH_ROW * 4)                 // 67584
#define OFF_ASL  (OFF_ASH + 128 * 20 * 4)           // 77824
#define OFF_BSH  (OFF_ASL + 128 * 20 * 4)           // 88064
#define OFF_BSL  (OFF_BSH + 16 * 136 * 4)           // 96768
#define SMEM_TOTAL_FUSED (OFF_BSL + 16 * 136 * 4)   // 105472

// Scratch (no allocations allowed in kernel_launch).
__device__ __align__(16) float g_z[(size_t)MAXN * D];
__device__ __align__(16) float g_h[(size_t)MAXN * D];
__device__ __align__(16) float g_stats[2 * D];
__device__ __align__(16) float g_scale[D];
__device__ __align__(16) float g_shift[D];
__device__ __align__(16) uint32_t g_WH[2 * MAXL * D * D];
__device__ __align__(16) uint32_t g_WL[2 * MAXL * D * D];
__device__ int g_idx_is64;
__device__ int g_deg[MAXN];
__device__ int g_row_ptr[MAXN + 1];
__device__ int g_cursor[MAXN];
__device__ int g_esrc[MAXE];
__device__ int g_bsum[MAX_SCAN_BLOCKS];
__device__ int g_bpre[MAX_SCAN_BLOCKS];

// ---------------------------------------------------------------------------
__device__ __forceinline__ int load_idx(const void* ei, int i) {
    if (g_idx_is64) return (int)__ldg(&((const long long*)ei)[i]);
    return __ldg(&((const int*)ei)[i]);
}

__global__ void zero_deg_probe(const void* ei, int E, int N) {
    int i = blockIdx.x * blockDim.x + threadIdx.x;
    if (i < N) g_deg[i] = 0;
    if (blockIdx.x == 0 && threadIdx.x == 0) {
        const long long* p = (const long long*)ei;
        int n = E < 64 ? E : 64;
        int ok = 1;
        for (int k = 0; k < n; ++k) {
            long long v = p[k];
            if (v < 0 || v >= N) { ok = 0; break; }
        }
        g_idx_is64 = ok;
    }
}

__global__ void hist_dst(const void* ei, int E, int N) {
    int i = blockIdx.x * blockDim.x + threadIdx.x;
    if (i >= E) return;
    int d = load_idx(ei, E + i);
    if ((unsigned)d < (unsigned)N) atomicAdd(&g_deg[d], 1);
}

__global__ void scan_block_sum(int N) {
    __shared__ int sh[256];
    int base = blockIdx.x * SCAN_TILE;
    int s = 0;
#pragma unroll
    for (int it = 0; it < 8; ++it) {
        int i = base + it * 256 + threadIdx.x;
        if (i < N) s += g_deg[i];
    }
    sh[threadIdx.x] = s;
    __syncthreads();
    for (int off = 128; off > 0; off >>= 1) {
        if (threadIdx.x < off) sh[threadIdx.x] += sh[threadIdx.x + off];
        __syncthreads();
    }
    if (threadIdx.x == 0) g_bsum[blockIdx.x] = sh[0];
}

__global__ void scan_bsums(int nb, int N) {
    __shared__ int sh[MAX_SCAN_BLOCKS];
    int v = (threadIdx.x < nb) ? g_bsum[threadIdx.x] : 0;
    sh[threadIdx.x] = v;
    __syncthreads();
    for (int off = 1; off < MAX_SCAN_BLOCKS; off <<= 1) {
        int t = (threadIdx.x >= off) ? sh[threadIdx.x - off] : 0;
        __syncthreads();
        sh[threadIdx.x] += t;
        __syncthreads();
    }
    if (threadIdx.x < nb) g_bpre[threadIdx.x] = sh[threadIdx.x] - v;
    if (threadIdx.x == nb - 1) g_row_ptr[N] = sh[threadIdx.x];
}

__global__ void scan_write(int N) {
    __shared__ int sh[256];
    int base = blockIdx.x * SCAN_TILE;
    int tstart = base + threadIdx.x * 8;
    int local[8];
    int s = 0;
#pragma unroll
    for (int j = 0; j < 8; ++j) {
        int i = tstart + j;
        int d = (i < N) ? g_deg[i] : 0;
        local[j] = s;
        s += d;
    }
    sh[threadIdx.x] = s;
    __syncthreads();
    for (int off = 1; off < 256; off <<= 1) {
        int t = (threadIdx.x >= off) ? sh[threadIdx.x - off] : 0;
        __syncthreads();
        sh[threadIdx.x] += t;
        __syncthreads();
    }
    int tpre = sh[threadIdx.x] - s + g_bpre[blockIdx.x];
#pragma unroll
    for (int j = 0; j < 8; ++j) {
        int i = tstart + j;
        if (i < N) {
            int r = tpre + local[j];
            g_row_ptr[i] = r;
            g_cursor[i] = r;
        }
    }
}

__global__ void fill_csr(const void* ei, int E, int N) {
    int i = blockIdx.x * blockDim.x + threadIdx.x;
    if (i >= E) return;
    int s = load_idx(ei, i);
    int d = load_idx(ei, E + i);
    if ((unsigned)s >= (unsigned)N || (unsigned)d >= (unsigned)N) return;
    int pos = atomicAdd(&g_cursor[d], 1);
    g_esrc[pos] = s;
}

// ---------------------------------------------------------------------------
__global__ void aggregate(const float4* __restrict__ x, float4* __restrict__ znew, int N) {
    int node = (blockIdx.x * blockDim.x + threadIdx.x) >> 5;
    int lane = threadIdx.x & 31;
    if (node >= N) return;
    float4 acc = x[(size_t)node * 32 + lane];
    int e = g_row_ptr[node], end = g_row_ptr[node + 1];
    for (; e + 3 < end; e += 4) {
        int s0 = __ldg(&g_esrc[e]);
        int s1 = __ldg(&g_esrc[e + 1]);
        int s2 = __ldg(&g_esrc[e + 2]);
        int s3 = __ldg(&g_esrc[e + 3]);
        float4 v0 = x[(size_t)s0 * 32 + lane];
        float4 v1 = x[(size_t)s1 * 32 + lane];
        float4 v2 = x[(size_t)s2 * 32 + lane];
        float4 v3 = x[(size_t)s3 * 32 + lane];
        acc.x += v0.x + v1.x + v2.x + v3.x;
        acc.y += v0.y + v1.y + v2.y + v3.y;
        acc.z += v0.z + v1.z + v2.z + v3.z;
        acc.w += v0.w + v1.w + v2.w + v3.w;
    }
    for (; e < end; ++e) {
        int s = __ldg(&g_esrc[e]);
        float4 v = x[(size_t)s * 32 + lane];
        acc.x += v.x; acc.y += v.y; acc.z += v.z; acc.w += v.w;
    }
    znew[(size_t)node * 32 + lane] = acc;
}

__global__ void aggregate_bn(const float4* __restrict__ zprev,
                             float4* __restrict__ outPrev,
                             float4* __restrict__ znew, int N) {
    int node = (blockIdx.x * blockDim.x + threadIdx.x) >> 5;
    int lane = threadIdx.x & 31;
    if (node >= N) return;
    float4 a = reinterpret_cast<const float4*>(g_scale)[lane];
    float4 b = reinterpret_cast<const float4*>(g_shift)[lane];

    float4 v = zprev[(size_t)node * 32 + lane];
    float4 own;
    own.x = fmaxf(fmaf(v.x, a.x, b.x), 0.f);
    own.y = fmaxf(fmaf(v.y, a.y, b.y), 0.f);
    own.z = fmaxf(fmaf(v.z, a.z, b.z), 0.f);
    own.w = fmaxf(fmaf(v.w, a.w, b.w), 0.f);
    outPrev[(size_t)node * 32 + lane] = own;

    float4 acc = own;
    int e = g_row_ptr[node], end = g_row_ptr[node + 1];
    for (; e + 1 < end; e += 2) {
        int s0 = __ldg(&g_esrc[e]);
        int s1 = __ldg(&g_esrc[e + 1]);
        float4 v0 = zprev[(size_t)s0 * 32 + lane];
        float4 v1 = zprev[(size_t)s1 * 32 + lane];
        acc.x += fmaxf(fmaf(v0.x, a.x, b.x), 0.f) + fmaxf(fmaf(v1.x, a.x, b.x), 0.f);
        acc.y += fmaxf(fmaf(v0.y, a.y, b.y), 0.f) + fmaxf(fmaf(v1.y, a.y, b.y), 0.f);
        acc.z += fmaxf(fmaf(v0.z, a.z, b.z), 0.f) + fmaxf(fmaf(v1.z, a.z, b.z), 0.f);
        acc.w += fmaxf(fmaf(v0.w, a.w, b.w), 0.f) + fmaxf(fmaf(v1.w, a.w, b.w), 0.f);
    }
    for (; e < end; ++e) {
        int s = __ldg(&g_esrc[e]);
        float4 vv = zprev[(size_t)s * 32 + lane];
        acc.x += fmaxf(fmaf(vv.x, a.x, b.x), 0.f);
        acc.y += fmaxf(fmaf(vv.y, a.y, b.y), 0.f);
        acc.z += fmaxf(fmaf(vv.z, a.z, b.z), 0.f);
        acc.w += fmaxf(fmaf(vv.w, a.w, b.w), 0.f);
    }
    znew[(size_t)node * 32 + lane] = acc;
}

// ---------------------------------------------------------------------------
__device__ __forceinline__ void split_tf32(float x, uint32_t& hi, uint32_t& lo) {
    uint32_t h;
    asm("cvt.rna.tf32.f32 %0, %1;" : "=r"(h) : "f"(x));
    float r = x - __uint_as_float(h);
    uint32_t l;
    asm("cvt.rna.tf32.f32 %0, %1;" : "=r"(l) : "f"(r));
    hi = h; lo = l;
}

__global__ void split_all_w(const float* __restrict__ W1,
                            const float* __restrict__ W2, int L) {
    int i = blockIdx.x * blockDim.x + threadIdx.x;
    if (blockIdx.x == 0 && threadIdx.x < 2 * D) g_stats[threadIdx.x] = 0.f;
    int total = L * D * D;
    if (i < total) {
        int l = i / (D * D), r = i % (D * D);
        uint32_t h, lo;
        split_tf32(W1[i], h, lo);
        int o = (0 * MAXL + l) * D * D + r;
        g_WH[o] = h; g_WL[o] = lo;
    } else if (i < 2 * total) {
        int j = i - total;
        int l = j / (D * D), r = j % (D * D);
        uint32_t h, lo;
        split_tf32(W2[j], h, lo);
        int o = (1 * MAXL + l) * D * D + r;
        g_WH[o] = h; g_WL[o] = lo;
    }
}

__device__ __forceinline__ void mma_tf32(float c[4], const uint32_t a[4], const uint32_t b[2]) {
    asm volatile(
        "mma.sync.aligned.m16n8k8.row.col.f32.tf32.tf32.f32 "
        "{%0,%1,%2,%3}, {%4,%5,%6,%7}, {%8,%9}, {%0,%1,%2,%3};"
        : "+f"(c[0]), "+f"(c[1]), "+f"(c[2]), "+f"(c[3])
        : "r"(a[0]), "r"(a[1]), "r"(a[2]), "r"(a[3]), "r"(b[0]), "r"(b[1]));
}

// ---------------------------------------------------------------------------
// Fused 2-layer MLP: z2 = relu(z@W1+b1)@W2+b2, one block = 128 rows.
// Phase 1 accumulates H, parks it (bias+relu) in fp32 smem, phase 2 consumes it.
// Epilogue 2 writes z2 and fused BN column stats. 3xTF32 throughout.
// ---------------------------------------------------------------------------
__device__ __forceinline__ void mma_block_step(
    const uint32_t* AsH, const uint32_t* AsL,
    const uint32_t* BsH, const uint32_t* BsL,
    float acc[2][8][4], int wr, int wc, int lq, int lg) {
#pragma unroll
    for (int ks = 0; ks < 2; ++ks) {
        int kb = ks * 8;
        uint32_t ah[2][4], al[2][4];
#pragma unroll
        for (int mt = 0; mt < 2; ++mt) {
            int r0 = wr * 32 + mt * 16 + lg;
            int kk = kb + lq;
            ah[mt][0] = AsH[r0 * 20 + kk];           al[mt][0] = AsL[r0 * 20 + kk];
            ah[mt][1] = AsH[(r0 + 8) * 20 + kk];     al[mt][1] = AsL[(r0 + 8) * 20 + kk];
            ah[mt][2] = AsH[r0 * 20 + kk + 4];       al[mt][2] = AsL[r0 * 20 + kk + 4];
            ah[mt][3] = AsH[(r0 + 8) * 20 + kk + 4]; al[mt][3] = AsL[(r0 + 8) * 20 + kk + 4];
        }
#pragma unroll
        for (int nt = 0; nt < 8; ++nt) {
            int n0 = wc * 64 + nt * 8 + lg;
            int kk = kb + lq;
            uint32_t bh[2], bl[2];
            bh[0] = BsH[kk * 136 + n0];       bl[0] = BsL[kk * 136 + n0];
            bh[1] = BsH[(kk + 4) * 136 + n0]; bl[1] = BsL[(kk + 4) * 136 + n0];
#pragma unroll
            for (int mt = 0; mt < 2; ++mt) {
                mma_tf32(acc[mt][nt], ah[mt], bh);
                mma_tf32(acc[mt][nt], al[mt], bh);
                mma_tf32(acc[mt][nt], ah[mt], bl);
            }
        }
    }
}

__global__ __launch_bounds__(256, 2) void mlp_fused(
    const float* __restrict__ A, float* __restrict__ C,
    int w1off, int w2off,
    const float* __restrict__ b1, const float* __restrict__ b2, int N) {

    extern __shared__ char smem[];
    float*    sH  = (float*)(smem + OFF_SH);      // [128][SH_ROW]
    uint32_t* AsH = (uint32_t*)(smem + OFF_ASH);  // [128][20]
    uint32_t* AsL = (uint32_t*)(smem + OFF_ASL);
    uint32_t* BsH = (uint32_t*)(smem + OFF_BSH);  // [16][136]
    uint32_t* BsL = (uint32_t*)(smem + OFF_BSL);

    int tid = threadIdx.x;
    int warp = tid >> 5, lane = tid & 31;
    int wr = warp >> 1;
    int wc = warp & 1;
    int rowBase = blockIdx.x * 128;
    int lq = lane & 3;
    int lg = lane >> 2;

    float acc[2][8][4] = {};

    // ---------------- Phase 1: H = z @ W1 ----------------
    for (int k0 = 0; k0 < D; k0 += 16) {
#pragma unroll
        for (int it = 0; it < 2; ++it) {
            int i = tid + it * 256;
            int row = rowBase + (i >> 2);
            int gr = row < N ? row : N - 1;
            float4 v = *reinterpret_cast<const float4*>(A + (size_t)gr * D + k0 + (i & 3) * 4);
            int r = i >> 2, c = (i & 3) * 4;
            uint32_t h, l;
            split_tf32(v.x, h, l); AsH[r * 20 + c + 0] = h; AsL[r * 20 + c + 0] = l;
            split_tf32(v.y, h, l); AsH[r * 20 + c + 1] = h; AsL[r * 20 + c + 1] = l;
            split_tf32(v.z, h, l); AsH[r * 20 + c + 2] = h; AsL[r * 20 + c + 2] = l;
            split_tf32(v.w, h, l); AsH[r * 20 + c + 3] = h; AsL[r * 20 + c + 3] = l;
        }
#pragma unroll
        for (int it = 0; it < 2; ++it) {
            int i = tid + it * 256;
            int row = i >> 5, c4 = (i & 31) * 4;
            *reinterpret_cast<uint4*>(&BsH[row * 136 + c4]) =
                *reinterpret_cast<const uint4*>(&g_WH[w1off + (size_t)(k0 + row) * D + c4]);
            *reinterpret_cast<uint4*>(&BsL[row * 136 + c4]) =
                *reinterpret_cast<const uint4*>(&g_WL[w1off + (size_t)(k0 + row) * D + c4]);
        }
        __syncthreads();
        mma_block_step(AsH, AsL, BsH, BsL, acc, wr, wc, lq, lg);
        __syncthreads();
    }

    // Epilogue 1: bias + relu -> sH (covers each element exactly once)
#pragma unroll
    for (int nt = 0; nt < 8; ++nt) {
        int col = wc * 64 + nt * 8 + 2 * lq;
        float b0 = b1[col], bcol1 = b1[col + 1];
#pragma unroll
        for (int mt = 0; mt < 2; ++mt) {
            int r0 = wr * 32 + mt * 16 + lg;
            int r1 = r0 + 8;
            sH[r0 * SH_ROW + col]     = fmaxf(acc[mt][nt][0] + b0, 0.f);
            sH[r0 * SH_ROW + col + 1] = fmaxf(acc[mt][nt][1] + bcol1, 0.f);
            sH[r1 * SH_ROW + col]     = fmaxf(acc[mt][nt][2] + b0, 0.f);
            sH[r1 * SH_ROW + col + 1] = fmaxf(acc[mt][nt][3] + bcol1, 0.f);
            acc[mt][nt][0] = 0.f; acc[mt][nt][1] = 0.f;
            acc[mt][nt][2] = 0.f; acc[mt][nt][3] = 0.f;
        }
    }
    __syncthreads();

    // ---------------- Phase 2: z2 = H @ W2 ----------------
    for (int k0 = 0; k0 < D; k0 += 16) {
#pragma unroll
        for (int it = 0; it < 2; ++it) {
            int i = tid + it * 256;
            int r = i >> 2, c = (i & 3) * 4;
            float4 v = *reinterpret_cast<const float4*>(&sH[r * SH_ROW + k0 + c]);
            uint32_t h, l;
            split_tf32(v.x, h, l); AsH[r * 20 + c + 0] = h; AsL[r * 20 + c + 0] = l;
            split_tf32(v.y, h, l); AsH[r * 20 + c + 1] = h; AsL[r * 20 + c + 1] = l;
            split_tf32(v.z, h, l); AsH[r * 20 + c + 2] = h; AsL[r * 20 + c + 2] = l;
            split_tf32(v.w, h, l); AsH[r * 20 + c + 3] = h; AsL[r * 20 + c + 3] = l;
        }
#pragma unroll
        for (int it = 0; it < 2; ++it) {
            int i = tid + it * 256;
            int row = i >> 5, c4 = (i & 31) * 4;
            *reinterpret_cast<uint4*>(&BsH[row * 136 + c4]) =
                *reinterpret_cast<const uint4*>(&g_WH[w2off + (size_t)(k0 + row) * D + c4]);
            *reinterpret_cast<uint4*>(&BsL[row * 136 + c4]) =
                *reinterpret_cast<const uint4*>(&g_WL[w2off + (size_t)(k0 + row) * D + c4]);
        }
        __syncthreads();
        mma_block_step(AsH, AsL, BsH, BsL, acc, wr, wc, lq, lg);
        __syncthreads();
    }

    // Epilogue 2: bias, store z2, fused BN stats
#pragma unroll
    for (int nt = 0; nt < 8; ++nt) {
        int col = wc * 64 + nt * 8 + 2 * lq;
        float b0 = b2[col], bcol1 = b2[col + 1];
        float s0 = 0.f, s1 = 0.f, q0 = 0.f, q1 = 0.f;
#pragma unroll
        for (int mt = 0; mt < 2; ++mt) {
            int r0 = rowBase + wr * 32 + mt * 16 + lg;
            int r1 = r0 + 8;
            float v00 = acc[mt][nt][0] + b0;
            float v01 = acc[mt][nt][1] + bcol1;
            float v10 = acc[mt][nt][2] + b0;
            float v11 = acc[mt][nt][3] + bcol1;
            if (r0 < N) {
                *reinterpret_cast<float2*>(C + (size_t)r0 * D + col) = make_float2(v00, v01);
                s0 += v00; s1 += v01; q0 += v00 * v00; q1 += v01 * v01;
            }
            if (r1 < N) {
                *reinterpret_cast<float2*>(C + (size_t)r1 * D + col) = make_float2(v10, v11);
                s0 += v10; s1 += v11; q0 += v10 * v10; q1 += v11 * v11;
            }
        }
#pragma unroll
        for (int m = 4; m <= 16; m <<= 1) {
            s0 += __shfl_xor_sync(0xffffffffu, s0, m);
            s1 += __shfl_xor_sync(0xffffffffu, s1, m);
            q0 += __shfl_xor_sync(0xffffffffu, q0, m);
            q1 += __shfl_xor_sync(0xffffffffu, q1, m);
        }
        if (lg == 0) {
            atomicAdd(&g_stats[col], s0);
            atomicAdd(&g_stats[col + 1], s1);
            atomicAdd(&g_stats[D + col], q0);
            atomicAdd(&g_stats[D + col + 1], q1);
        }
    }
}

// ---------------------------------------------------------------------------
__global__ void bn_finalize(const float* __restrict__ gamma,
                            const float* __restrict__ beta, float invN) {
    int c = threadIdx.x;
    float s = g_stats[c], q = g_stats[D + c];
    float mean = s * invN;
    float var = fmaxf(q * invN - mean * mean, 0.f);
    float a = gamma[c] * rsqrtf(var + 1e-5f);
    g_scale[c] = a;
    g_shift[c] = beta[c] - mean * a;
    g_stats[c] = 0.f;
    g_stats[D + c] = 0.f;
}

__global__ void bn_relu(const float4* __restrict__ z2, float4* __restrict__ y, int n4) {
    int i = blockIdx.x * blockDim.x + threadIdx.x;
    if (i >= n4) return;
    int c = i & (D / 4 - 1);
    float4 a = *reinterpret_cast<const float4*>(&g_scale[c * 4]);
    float4 b = *reinterpret_cast<const float4*>(&g_shift[c * 4]);
    float4 v = z2[i];
    v.x = fmaxf(fmaf(v.x, a.x, b.x), 0.f);
    v.y = fmaxf(fmaf(v.y, a.y, b.y), 0.f);
    v.z = fmaxf(fmaf(v.z, a.z, b.z), 0.f);
    v.w = fmaxf(fmaf(v.w, a.w, b.w), 0.f);
    y[i] = v;
}

// ---------------------------------------------------------------------------
extern "C" void kernel_launch(void* const* d_in, const int* in_sizes, int n_in,
                              void* d_out, int out_size) {
    const float* h     = (const float*)d_in[0];
    const void*  ei    = d_in[1];
    const float* W1    = (const float*)d_in[2];
    const float* b1    = (const float*)d_in[3];
    const float* W2    = (const float*)d_in[4];
    const float* b2    = (const float*)d_in[5];
    const float* gamma = (const float*)d_in[6];
    const float* beta  = (const float*)d_in[7];
    float*       out   = (float*)d_out;

    int N = in_sizes[0] / D;
    int E = in_sizes[1] / 2;
    int L = in_sizes[2] / (D * D);

    int n4 = N * (D / 4);
    int vecBlocks = (n4 + 255) / 256;
    int eBlocks = (E + 255) / 256;
    int nBlocks = (N + 255) / 256;
    int aggBlocks = (N * 32 + 255) / 256;
    int gemmBlocks = (N + 127) / 128;
    int scanBlocks = (N + SCAN_TILE - 1) / SCAN_TILE;

    static int smem_set = 0;
    if (!smem_set) {
        cudaFuncSetAttribute(mlp_fused, cudaFuncAttributeMaxDynamicSharedMemorySize,
                             SMEM_TOTAL_FUSED);
        smem_set = 1;
    }

    void *pz = nullptr, *ph = nullptr;
    cudaGetSymbolAddress(&pz, g_z);
    cudaGetSymbolAddress(&ph, g_h);
    float* A = (float*)pz;
    float* B = (float*)ph;

    zero_deg_probe<<<nBlocks, 256>>>(ei, E, N);
    hist_dst<<<eBlocks, 256>>>(ei, E, N);
    scan_block_sum<<<scanBlocks, 256>>>(N);
    scan_bsums<<<1, MAX_SCAN_BLOCKS>>>(scanBlocks, N);
    scan_write<<<scanBlocks, 256>>>(N);
    fill_csr<<<eBlocks, 256>>>(ei, E, N);
    split_all_w<<<(2 * L * D * D + 255) / 256, 256>>>(W1, W2, L);

    for (int l = 0; l < L; ++l) {
        int w1off = (0 * MAXL + l) * D * D;
        int w2off = (1 * MAXL + l) * D * D;
        if (l == 0) {
            aggregate<<<aggBlocks, 256>>>((const float4*)h, (float4*)A, N);
            mlp_fused<<<gemmBlocks, 256, SMEM_TOTAL_FUSED>>>(
                A, B, w1off, w2off, b1 + l * D, b2 + l * D, N);
            bn_finalize<<<1, D>>>(gamma + l * D, beta + l * D, 1.0f / (float)N);
            // z2 lives in B -> make A hold z2 for next layer
            float* t = A; A = B; B = t;
        } else {
            float* yPrev = out + (size_t)(l - 1) * N * D;
            aggregate_bn<<<aggBlocks, 256>>>((const float4*)A, (float4*)yPrev, (float4*)B, N);
            mlp_fused<<<gemmBlocks, 256, SMEM_TOTAL_FUSED>>>(
                B, A, w1off, w2off, b1 + l * D, b2 + l * D, N);
            bn_finalize<<<1, D>>>(gamma + l * D, beta + l * D, 1.0f / (float)N);
            // z2 lives in A (already the read buffer for next layer)
        }
    }
    bn_relu<<<vecBlocks, 256>>>((const float4*)A, (float4*)(out + (size_t)(L - 1) * N * D), n4);
}